// round 1
// baseline (speedup 1.0000x reference)
#include <cuda_runtime.h>
#include <cuda_bf16.h>

#define NN 200000
#define FIN 128

// Scratch (static __device__ — no allocation allowed)
__device__ float g_dinv[NN];          // deg -> rsqrt(deg) in place
__device__ float g_g1[NN * 12];       // (x@W1)*dinv
__device__ float g_acc1[NN * 12];
__device__ float g_g2[NN * 24];       // (h1@W2)*dinv
__device__ float g_acc2[NN * 24];
__device__ int   g_idx64;             // 1 if edge_index is int64, 0 if int32

// ---------------------------------------------------------------------------
// Detect edge index dtype: if int64 (values < 2^31), every odd 32-bit word is 0.
__global__ void k_detect(const int* ei) {
    if (blockIdx.x == 0 && threadIdx.x == 0) {
        int acc = 0;
        #pragma unroll
        for (int i = 0; i < 32; ++i) acc |= ei[2 * i + 1];
        g_idx64 = (acc == 0) ? 1 : 0;
    }
}

// ---------------------------------------------------------------------------
// Init: deg=1 (self loop), acc1=0, acc2=0
__global__ void k_init(int n) {
    int i = blockIdx.x * blockDim.x + threadIdx.x;
    if (i < n * 24) g_acc2[i] = 0.0f;
    if (i < n * 12) g_acc1[i] = 0.0f;
    if (i < n)      g_dinv[i] = 1.0f;
}

// ---------------------------------------------------------------------------
// Degree accumulation over targets (col = second half of edge_index)
__global__ void k_deg(const void* __restrict__ ei, int ecnt) {
    int e = blockIdx.x * blockDim.x + threadIdx.x;
    if (e >= ecnt) return;
    int c;
    if (g_idx64) c = (int)((const long long*)ei)[(long long)ecnt + e];
    else         c = ((const int*)ei)[ecnt + e];
    atomicAdd(&g_dinv[c], 1.0f);
}

__global__ void k_rsqrt(int n) {
    int i = blockIdx.x * blockDim.x + threadIdx.x;
    if (i < n) g_dinv[i] = rsqrtf(g_dinv[i]);
}

// ---------------------------------------------------------------------------
// GEMM1: g1[n][j] = dinv[n] * sum_k x[n][k] * W1[k][j]   (128 -> 12)
// 2 nodes per thread to amortize shared-memory W loads.
__device__ __forceinline__ float comp4(const float4& v, int kk) {
    return kk == 0 ? v.x : kk == 1 ? v.y : kk == 2 ? v.z : v.w;
}

__global__ void k_gemm1(const float* __restrict__ x, const float* __restrict__ W1, int n) {
    __shared__ float Ws[FIN * 12];
    for (int i = threadIdx.x; i < FIN * 12; i += blockDim.x) Ws[i] = W1[i];
    __syncthreads();

    int g  = blockIdx.x * blockDim.x + threadIdx.x;
    int n0 = g * 2;
    if (n0 >= n) return;
    bool two = (n0 + 1 < n);

    float acc0[12], acc1v[12];
    #pragma unroll
    for (int j = 0; j < 12; ++j) { acc0[j] = 0.0f; acc1v[j] = 0.0f; }

    const float4* xr0 = (const float4*)x + (size_t)n0 * (FIN / 4);
    const float4* xr1 = xr0 + (FIN / 4);

    #pragma unroll 4
    for (int k4 = 0; k4 < FIN / 4; ++k4) {
        float4 a = __ldcs(xr0 + k4);
        float4 b = two ? __ldcs(xr1 + k4) : make_float4(0.f, 0.f, 0.f, 0.f);
        #pragma unroll
        for (int kk = 0; kk < 4; ++kk) {
            const float4* wp = (const float4*)(Ws + (k4 * 4 + kk) * 12);
            float4 w0 = wp[0], w1 = wp[1], w2 = wp[2];
            float xa = comp4(a, kk);
            float xb = comp4(b, kk);
            acc0[0]  += xa * w0.x; acc0[1]  += xa * w0.y; acc0[2]  += xa * w0.z; acc0[3]  += xa * w0.w;
            acc0[4]  += xa * w1.x; acc0[5]  += xa * w1.y; acc0[6]  += xa * w1.z; acc0[7]  += xa * w1.w;
            acc0[8]  += xa * w2.x; acc0[9]  += xa * w2.y; acc0[10] += xa * w2.z; acc0[11] += xa * w2.w;
            acc1v[0]  += xb * w0.x; acc1v[1]  += xb * w0.y; acc1v[2]  += xb * w0.z; acc1v[3]  += xb * w0.w;
            acc1v[4]  += xb * w1.x; acc1v[5]  += xb * w1.y; acc1v[6]  += xb * w1.z; acc1v[7]  += xb * w1.w;
            acc1v[8]  += xb * w2.x; acc1v[9]  += xb * w2.y; acc1v[10] += xb * w2.z; acc1v[11] += xb * w2.w;
        }
    }

    {
        float dn = g_dinv[n0];
        float4* out4 = (float4*)g_g1 + (size_t)n0 * 3;
        out4[0] = make_float4(acc0[0] * dn, acc0[1] * dn, acc0[2]  * dn, acc0[3]  * dn);
        out4[1] = make_float4(acc0[4] * dn, acc0[5] * dn, acc0[6]  * dn, acc0[7]  * dn);
        out4[2] = make_float4(acc0[8] * dn, acc0[9] * dn, acc0[10] * dn, acc0[11] * dn);
    }
    if (two) {
        float dn = g_dinv[n0 + 1];
        float4* out4 = (float4*)g_g1 + (size_t)(n0 + 1) * 3;
        out4[0] = make_float4(acc1v[0] * dn, acc1v[1] * dn, acc1v[2]  * dn, acc1v[3]  * dn);
        out4[1] = make_float4(acc1v[4] * dn, acc1v[5] * dn, acc1v[6]  * dn, acc1v[7]  * dn);
        out4[2] = make_float4(acc1v[8] * dn, acc1v[9] * dn, acc1v[10] * dn, acc1v[11] * dn);
    }
}

// ---------------------------------------------------------------------------
// Scatter layer 1: acc1[col] += g1[row]   (12 floats = 3x float4 atomics)
__global__ void k_scatter1(const void* __restrict__ ei, int ecnt) {
    int e = blockIdx.x * blockDim.x + threadIdx.x;
    if (e >= ecnt) return;
    int r, c;
    if (g_idx64) {
        const long long* p = (const long long*)ei;
        r = (int)p[e];
        c = (int)p[(long long)ecnt + e];
    } else {
        const int* p = (const int*)ei;
        r = p[e];
        c = p[ecnt + e];
    }
    const float4* gp = (const float4*)g_g1 + (size_t)r * 3;
    float4 v0 = __ldg(gp), v1 = __ldg(gp + 1), v2 = __ldg(gp + 2);
    float4* ap = (float4*)g_acc1 + (size_t)c * 3;
    atomicAdd(ap,     v0);
    atomicAdd(ap + 1, v1);
    atomicAdd(ap + 2, v2);
}

// ---------------------------------------------------------------------------
// Layer-2 node work: h1 = relu(dinv*(acc1+g1)+b1); g2 = (h1@W2)*dinv  (12 -> 24)
__global__ void k_layer2(const float* __restrict__ b1v, const float* __restrict__ W2, int n) {
    __shared__ float Ws[12 * 24];
    __shared__ float bs[12];
    for (int i = threadIdx.x; i < 12 * 24; i += blockDim.x) Ws[i] = W2[i];
    if (threadIdx.x < 12) bs[threadIdx.x] = b1v[threadIdx.x];
    __syncthreads();

    int node = blockIdx.x * blockDim.x + threadIdx.x;
    if (node >= n) return;
    float dn = g_dinv[node];

    float h[12];
    const float4* a4 = (const float4*)g_acc1 + (size_t)node * 3;
    const float4* g4 = (const float4*)g_g1  + (size_t)node * 3;
    #pragma unroll
    for (int q = 0; q < 3; ++q) {
        float4 av = a4[q], gv = g4[q];
        h[q * 4 + 0] = fmaxf(dn * (av.x + gv.x) + bs[q * 4 + 0], 0.0f);
        h[q * 4 + 1] = fmaxf(dn * (av.y + gv.y) + bs[q * 4 + 1], 0.0f);
        h[q * 4 + 2] = fmaxf(dn * (av.z + gv.z) + bs[q * 4 + 2], 0.0f);
        h[q * 4 + 3] = fmaxf(dn * (av.w + gv.w) + bs[q * 4 + 3], 0.0f);
    }

    float o[24];
    #pragma unroll
    for (int j2 = 0; j2 < 24; ++j2) o[j2] = 0.0f;
    #pragma unroll
    for (int j = 0; j < 12; ++j) {
        float hv = h[j];
        const float* wr = Ws + j * 24;
        #pragma unroll
        for (int j2 = 0; j2 < 24; ++j2) o[j2] += hv * wr[j2];
    }

    float4* out4 = (float4*)g_g2 + (size_t)node * 6;
    #pragma unroll
    for (int q = 0; q < 6; ++q)
        out4[q] = make_float4(o[q * 4] * dn, o[q * 4 + 1] * dn, o[q * 4 + 2] * dn, o[q * 4 + 3] * dn);
}

// ---------------------------------------------------------------------------
// Scatter layer 2: acc2[col] += g2[row]   (24 floats = 6x float4 atomics)
__global__ void k_scatter2(const void* __restrict__ ei, int ecnt) {
    int e = blockIdx.x * blockDim.x + threadIdx.x;
    if (e >= ecnt) return;
    int r, c;
    if (g_idx64) {
        const long long* p = (const long long*)ei;
        r = (int)p[e];
        c = (int)p[(long long)ecnt + e];
    } else {
        const int* p = (const int*)ei;
        r = p[e];
        c = p[ecnt + e];
    }
    const float4* gp = (const float4*)g_g2 + (size_t)r * 6;
    float4* ap = (float4*)g_acc2 + (size_t)c * 6;
    #pragma unroll
    for (int q = 0; q < 6; ++q) {
        float4 v = __ldg(gp + q);
        atomicAdd(ap + q, v);
    }
}

// ---------------------------------------------------------------------------
// Final: h2 = relu(dinv*(acc2+g2)+b2); h3 = relu(h2@Wf1+bf1); out = h3@Wf2+bf2
__global__ void k_final(const float* __restrict__ b2v,
                        const float* __restrict__ Wf1, const float* __restrict__ bf1,
                        const float* __restrict__ Wf2, const float* __restrict__ bf2,
                        float* __restrict__ out, int n) {
    __shared__ float W1s[24 * 32];
    __shared__ float W2s[32 * 2];
    __shared__ float b2s[24], bf1s[32], bf2s[2];
    for (int i = threadIdx.x; i < 24 * 32; i += blockDim.x) W1s[i] = Wf1[i];
    if (threadIdx.x < 64) W2s[threadIdx.x] = Wf2[threadIdx.x];
    if (threadIdx.x < 24) b2s[threadIdx.x] = b2v[threadIdx.x];
    if (threadIdx.x < 32) bf1s[threadIdx.x] = bf1[threadIdx.x];
    if (threadIdx.x < 2)  bf2s[threadIdx.x] = bf2[threadIdx.x];
    __syncthreads();

    int node = blockIdx.x * blockDim.x + threadIdx.x;
    if (node >= n) return;
    float dn = g_dinv[node];

    float h2[24];
    const float4* a4 = (const float4*)g_acc2 + (size_t)node * 6;
    const float4* g4 = (const float4*)g_g2  + (size_t)node * 6;
    #pragma unroll
    for (int q = 0; q < 6; ++q) {
        float4 av = a4[q], gv = g4[q];
        h2[q * 4 + 0] = fmaxf(dn * (av.x + gv.x) + b2s[q * 4 + 0], 0.0f);
        h2[q * 4 + 1] = fmaxf(dn * (av.y + gv.y) + b2s[q * 4 + 1], 0.0f);
        h2[q * 4 + 2] = fmaxf(dn * (av.z + gv.z) + b2s[q * 4 + 2], 0.0f);
        h2[q * 4 + 3] = fmaxf(dn * (av.w + gv.w) + b2s[q * 4 + 3], 0.0f);
    }

    float h3[32];
    #pragma unroll
    for (int o = 0; o < 32; ++o) h3[o] = bf1s[o];
    #pragma unroll
    for (int j = 0; j < 24; ++j) {
        float hv = h2[j];
        const float* wr = W1s + j * 32;
        #pragma unroll
        for (int o = 0; o < 32; ++o) h3[o] += hv * wr[o];
    }
    #pragma unroll
    for (int o = 0; o < 32; ++o) h3[o] = fmaxf(h3[o], 0.0f);

    float o0 = bf2s[0], o1 = bf2s[1];
    #pragma unroll
    for (int o = 0; o < 32; ++o) {
        o0 += h3[o] * W2s[o * 2 + 0];
        o1 += h3[o] * W2s[o * 2 + 1];
    }
    ((float2*)out)[node] = make_float2(o0, o1);
}

// ---------------------------------------------------------------------------
extern "C" void kernel_launch(void* const* d_in, const int* in_sizes, int n_in,
                              void* d_out, int out_size) {
    const float* x   = (const float*)d_in[0];
    const void*  ei  = d_in[1];
    const float* W1  = (const float*)d_in[2];
    const float* b1  = (const float*)d_in[3];
    const float* W2  = (const float*)d_in[4];
    const float* b2  = (const float*)d_in[5];
    const float* Wf1 = (const float*)d_in[6];
    const float* bf1 = (const float*)d_in[7];
    const float* Wf2 = (const float*)d_in[8];
    const float* bf2 = (const float*)d_in[9];
    float* out = (float*)d_out;

    const int n = in_sizes[0] / FIN;       // 200000
    const int e = in_sizes[1] / 2;         // 6400000

    const int T = 256;
    k_detect<<<1, 32>>>((const int*)ei);
    k_init<<<(n * 24 + T - 1) / T, T>>>(n);
    k_deg<<<(e + T - 1) / T, T>>>(ei, e);
    k_rsqrt<<<(n + T - 1) / T, T>>>(n);
    k_gemm1<<<((n + 1) / 2 + T - 1) / T, T>>>(x, W1, n);
    k_scatter1<<<(e + T - 1) / T, T>>>(ei, e);
    k_layer2<<<(n + T - 1) / T, T>>>(b1, W2, n);
    k_scatter2<<<(e + T - 1) / T, T>>>(ei, e);
    k_final<<<(n + T - 1) / T, T>>>(b2, Wf1, bf1, Wf2, bf2, out, n);
}

// round 3
// speedup vs baseline: 1.3036x; 1.3036x over previous
#include <cuda_runtime.h>
#include <cuda_bf16.h>

#define NN 200000
#define EE 6400000
#define FIN 128

// Scratch (static __device__ — no allocation allowed)
__device__ float g_dinv[NN];            // deg -> rsqrt(deg) in place
__device__ float g_g1[NN * 12];         // (x@W1)*dinv
__device__ float g_acc1[NN * 12];
__device__ float g_u[NN * 12];          // relu(layer1)*dinv  (pre-W2, low-rank trick)
__device__ float g_acc2[NN * 12];
__device__ int4  g_edges4[(EE + 1) / 2];// packed int32 edges: {r0,c0,r1,c1}
__device__ int   g_idx64;               // 1 if edge_index is int64, 0 if int32

// ---------------------------------------------------------------------------
// Detect edge index dtype: if int64 (values < 2^31), every odd 32-bit word is 0.
__global__ void k_detect(const int* ei) {
    if (blockIdx.x == 0 && threadIdx.x == 0) {
        int acc = 0;
        #pragma unroll
        for (int i = 0; i < 32; ++i) acc |= ei[2 * i + 1];
        g_idx64 = (acc == 0) ? 1 : 0;
    }
}

// ---------------------------------------------------------------------------
// Init: deg=1 (self loop), acc1=0, acc2=0
__global__ void k_init(int n) {
    int i = blockIdx.x * blockDim.x + threadIdx.x;
    if (i < n * 12) { g_acc1[i] = 0.0f; g_acc2[i] = 0.0f; }
    if (i < n)      g_dinv[i] = 1.0f;
}

// ---------------------------------------------------------------------------
// Degree accumulation over targets + convert edge index to packed int32 pairs.
// 2 edges per thread; writes one int4.
__global__ void k_deg_convert(const void* __restrict__ ei, int ecnt) {
    int t  = blockIdx.x * blockDim.x + threadIdx.x;
    int e0 = t * 2;
    if (e0 >= ecnt) return;
    bool two = (e0 + 1 < ecnt);
    int r0, c0, r1 = 0, c1 = 0;
    if (g_idx64) {
        const long long* p = (const long long*)ei;
        r0 = (int)p[e0];
        c0 = (int)p[(long long)ecnt + e0];
        if (two) { r1 = (int)p[e0 + 1]; c1 = (int)p[(long long)ecnt + e0 + 1]; }
    } else {
        const int* p = (const int*)ei;
        r0 = p[e0];
        c0 = p[ecnt + e0];
        if (two) { r1 = p[e0 + 1]; c1 = p[ecnt + e0 + 1]; }
    }
    g_edges4[t] = make_int4(r0, c0, r1, c1);
    atomicAdd(&g_dinv[c0], 1.0f);
    if (two) atomicAdd(&g_dinv[c1], 1.0f);
}

__global__ void k_rsqrt(int n) {
    int i = blockIdx.x * blockDim.x + threadIdx.x;
    if (i < n) g_dinv[i] = rsqrtf(g_dinv[i]);
}

// ---------------------------------------------------------------------------
// GEMM1: g1[n][j] = dinv[n] * sum_k x[n][k] * W1[k][j]   (128 -> 12)
__device__ __forceinline__ float comp4(const float4& v, int kk) {
    return kk == 0 ? v.x : kk == 1 ? v.y : kk == 2 ? v.z : v.w;
}

__global__ void k_gemm1(const float* __restrict__ x, const float* __restrict__ W1, int n) {
    __shared__ float Ws[FIN * 12];
    for (int i = threadIdx.x; i < FIN * 12; i += blockDim.x) Ws[i] = W1[i];
    __syncthreads();

    int g  = blockIdx.x * blockDim.x + threadIdx.x;
    int n0 = g * 2;
    if (n0 >= n) return;
    bool two = (n0 + 1 < n);

    float acc0[12], acc1v[12];
    #pragma unroll
    for (int j = 0; j < 12; ++j) { acc0[j] = 0.0f; acc1v[j] = 0.0f; }

    const float4* xr0 = (const float4*)x + (size_t)n0 * (FIN / 4);
    const float4* xr1 = xr0 + (FIN / 4);

    #pragma unroll 4
    for (int k4 = 0; k4 < FIN / 4; ++k4) {
        float4 a = __ldcs(xr0 + k4);
        float4 b = two ? __ldcs(xr1 + k4) : make_float4(0.f, 0.f, 0.f, 0.f);
        #pragma unroll
        for (int kk = 0; kk < 4; ++kk) {
            const float4* wp = (const float4*)(Ws + (k4 * 4 + kk) * 12);
            float4 w0 = wp[0], w1 = wp[1], w2 = wp[2];
            float xa = comp4(a, kk);
            float xb = comp4(b, kk);
            acc0[0]  += xa * w0.x; acc0[1]  += xa * w0.y; acc0[2]  += xa * w0.z; acc0[3]  += xa * w0.w;
            acc0[4]  += xa * w1.x; acc0[5]  += xa * w1.y; acc0[6]  += xa * w1.z; acc0[7]  += xa * w1.w;
            acc0[8]  += xa * w2.x; acc0[9]  += xa * w2.y; acc0[10] += xa * w2.z; acc0[11] += xa * w2.w;
            acc1v[0]  += xb * w0.x; acc1v[1]  += xb * w0.y; acc1v[2]  += xb * w0.z; acc1v[3]  += xb * w0.w;
            acc1v[4]  += xb * w1.x; acc1v[5]  += xb * w1.y; acc1v[6]  += xb * w1.z; acc1v[7]  += xb * w1.w;
            acc1v[8]  += xb * w2.x; acc1v[9]  += xb * w2.y; acc1v[10] += xb * w2.z; acc1v[11] += xb * w2.w;
        }
    }

    {
        float dn = g_dinv[n0];
        float4* out4 = (float4*)g_g1 + (size_t)n0 * 3;
        out4[0] = make_float4(acc0[0] * dn, acc0[1] * dn, acc0[2]  * dn, acc0[3]  * dn);
        out4[1] = make_float4(acc0[4] * dn, acc0[5] * dn, acc0[6]  * dn, acc0[7]  * dn);
        out4[2] = make_float4(acc0[8] * dn, acc0[9] * dn, acc0[10] * dn, acc0[11] * dn);
    }
    if (two) {
        float dn = g_dinv[n0 + 1];
        float4* out4 = (float4*)g_g1 + (size_t)(n0 + 1) * 3;
        out4[0] = make_float4(acc1v[0] * dn, acc1v[1] * dn, acc1v[2]  * dn, acc1v[3]  * dn);
        out4[1] = make_float4(acc1v[4] * dn, acc1v[5] * dn, acc1v[6]  * dn, acc1v[7]  * dn);
        out4[2] = make_float4(acc1v[8] * dn, acc1v[9] * dn, acc1v[10] * dn, acc1v[11] * dn);
    }
}

// ---------------------------------------------------------------------------
// Generic 12-wide scatter: acc[col] += src[row]. 2 edges/thread, int4 edge load.
// PASS=0: g1 -> acc1 ; PASS=1: u -> acc2
template <int PASS>
__global__ void k_scatter12(int ecnt) {
    const float4* __restrict__ src = (const float4*)(PASS == 0 ? g_g1 : g_u);
    float4* acc = (float4*)(PASS == 0 ? g_acc1 : g_acc2);

    int t  = blockIdx.x * blockDim.x + threadIdx.x;
    int e0 = t * 2;
    if (e0 >= ecnt) return;
    int4 rc = __ldg(&g_edges4[t]);

    const float4* s0 = src + (size_t)rc.x * 3;
    float4 a0 = __ldg(s0), a1 = __ldg(s0 + 1), a2 = __ldg(s0 + 2);

    if (e0 + 1 < ecnt) {
        const float4* s1 = src + (size_t)rc.z * 3;
        float4 b0 = __ldg(s1), b1 = __ldg(s1 + 1), b2 = __ldg(s1 + 2);
        float4* d0 = acc + (size_t)rc.y * 3;
        float4* d1 = acc + (size_t)rc.w * 3;
        atomicAdd(d0,     a0);
        atomicAdd(d0 + 1, a1);
        atomicAdd(d0 + 2, a2);
        atomicAdd(d1,     b0);
        atomicAdd(d1 + 1, b1);
        atomicAdd(d1 + 2, b2);
    } else {
        float4* d0 = acc + (size_t)rc.y * 3;
        atomicAdd(d0,     a0);
        atomicAdd(d0 + 1, a1);
        atomicAdd(d0 + 2, a2);
    }
}

// ---------------------------------------------------------------------------
// u[node] = relu(dinv*(acc1+g1)+b1) * dinv      (12 floats; pre-W2 low-rank form)
__global__ void k_u(const float* __restrict__ b1v, int n) {
    __shared__ float bs[12];
    if (threadIdx.x < 12) bs[threadIdx.x] = b1v[threadIdx.x];
    __syncthreads();

    int node = blockIdx.x * blockDim.x + threadIdx.x;
    if (node >= n) return;
    float dn = g_dinv[node];

    const float4* a4 = (const float4*)g_acc1 + (size_t)node * 3;
    const float4* g4 = (const float4*)g_g1  + (size_t)node * 3;
    float4* out4 = (float4*)g_u + (size_t)node * 3;
    #pragma unroll
    for (int q = 0; q < 3; ++q) {
        float4 av = a4[q], gv = g4[q];
        float4 r;
        r.x = fmaxf(dn * (av.x + gv.x) + bs[q * 4 + 0], 0.0f) * dn;
        r.y = fmaxf(dn * (av.y + gv.y) + bs[q * 4 + 1], 0.0f) * dn;
        r.z = fmaxf(dn * (av.z + gv.z) + bs[q * 4 + 2], 0.0f) * dn;
        r.w = fmaxf(dn * (av.w + gv.w) + bs[q * 4 + 3], 0.0f) * dn;
        out4[q] = r;
    }
}

// ---------------------------------------------------------------------------
// Final: v = (acc2+u)*dinv; h2 = relu(v@W2+b2); h3 = relu(h2@Wf1+bf1); out = h3@Wf2+bf2
__global__ void k_final(const float* __restrict__ W2, const float* __restrict__ b2v,
                        const float* __restrict__ Wf1, const float* __restrict__ bf1,
                        const float* __restrict__ Wf2, const float* __restrict__ bf2,
                        float* __restrict__ out, int n) {
    __shared__ float W2s[12 * 24];
    __shared__ float Wf1s[24 * 32];
    __shared__ float Wf2s[32 * 2];
    __shared__ float b2s[24], bf1s[32], bf2s[2];
    for (int i = threadIdx.x; i < 12 * 24; i += blockDim.x) W2s[i] = W2[i];
    for (int i = threadIdx.x; i < 24 * 32; i += blockDim.x) Wf1s[i] = Wf1[i];
    if (threadIdx.x < 64) Wf2s[threadIdx.x] = Wf2[threadIdx.x];
    if (threadIdx.x < 24) b2s[threadIdx.x] = b2v[threadIdx.x];
    if (threadIdx.x < 32) bf1s[threadIdx.x] = bf1[threadIdx.x];
    if (threadIdx.x < 2)  bf2s[threadIdx.x] = bf2[threadIdx.x];
    __syncthreads();

    int node = blockIdx.x * blockDim.x + threadIdx.x;
    if (node >= n) return;
    float dn = g_dinv[node];

    float v[12];
    const float4* a4 = (const float4*)g_acc2 + (size_t)node * 3;
    const float4* u4 = (const float4*)g_u   + (size_t)node * 3;
    #pragma unroll
    for (int q = 0; q < 3; ++q) {
        float4 av = a4[q], uv = u4[q];
        v[q * 4 + 0] = dn * (av.x + uv.x);
        v[q * 4 + 1] = dn * (av.y + uv.y);
        v[q * 4 + 2] = dn * (av.z + uv.z);
        v[q * 4 + 3] = dn * (av.w + uv.w);
    }

    float h2[24];
    #pragma unroll
    for (int j2 = 0; j2 < 24; ++j2) h2[j2] = b2s[j2];
    #pragma unroll
    for (int j = 0; j < 12; ++j) {
        float hv = v[j];
        const float* wr = W2s + j * 24;
        #pragma unroll
        for (int j2 = 0; j2 < 24; ++j2) h2[j2] += hv * wr[j2];
    }
    #pragma unroll
    for (int j2 = 0; j2 < 24; ++j2) h2[j2] = fmaxf(h2[j2], 0.0f);

    float h3[32];
    #pragma unroll
    for (int o = 0; o < 32; ++o) h3[o] = bf1s[o];
    #pragma unroll
    for (int j = 0; j < 24; ++j) {
        float hv = h2[j];
        const float* wr = Wf1s + j * 32;
        #pragma unroll
        for (int o = 0; o < 32; ++o) h3[o] += hv * wr[o];
    }
    #pragma unroll
    for (int o = 0; o < 32; ++o) h3[o] = fmaxf(h3[o], 0.0f);

    float o0 = bf2s[0], o1 = bf2s[1];
    #pragma unroll
    for (int o = 0; o < 32; ++o) {
        o0 += h3[o] * Wf2s[o * 2 + 0];
        o1 += h3[o] * Wf2s[o * 2 + 1];
    }
    ((float2*)out)[node] = make_float2(o0, o1);
}

// ---------------------------------------------------------------------------
extern "C" void kernel_launch(void* const* d_in, const int* in_sizes, int n_in,
                              void* d_out, int out_size) {
    const float* x   = (const float*)d_in[0];
    const void*  ei  = d_in[1];
    const float* W1  = (const float*)d_in[2];
    const float* b1  = (const float*)d_in[3];
    const float* W2  = (const float*)d_in[4];
    const float* b2  = (const float*)d_in[5];
    const float* Wf1 = (const float*)d_in[6];
    const float* bf1 = (const float*)d_in[7];
    const float* Wf2 = (const float*)d_in[8];
    const float* bf2 = (const float*)d_in[9];
    float* out = (float*)d_out;

    const int n = in_sizes[0] / FIN;       // 200000
    const int e = in_sizes[1] / 2;         // 6400000
    const int epairs = (e + 1) / 2;

    const int T = 256;
    k_detect<<<1, 32>>>((const int*)ei);
    k_init<<<(n * 12 + T - 1) / T, T>>>(n);
    k_deg_convert<<<(epairs + T - 1) / T, T>>>(ei, e);
    k_rsqrt<<<(n + T - 1) / T, T>>>(n);
    k_gemm1<<<((n + 1) / 2 + T - 1) / T, T>>>(x, W1, n);
    k_scatter12<0><<<(epairs + T - 1) / T, T>>>(e);
    k_u<<<(n + T - 1) / T, T>>>(b1, n);
    k_scatter12<1><<<(epairs + T - 1) / T, T>>>(e);
    k_final<<<(n + T - 1) / T, T>>>(W2, b2, Wf1, bf1, Wf2, bf2, out, n);
}

// round 4
// speedup vs baseline: 1.3948x; 1.0699x over previous
#include <cuda_runtime.h>
#include <cuda_bf16.h>

#define NN 200000
#define EE 6400000
#define FIN 128

#define SCAN_T 256
#define SCAN_E 8
#define SCAN_CHUNK (SCAN_T * SCAN_E)                    // 2048
#define NB1 ((NN + SCAN_CHUNK - 1) / SCAN_CHUNK)        // blocks in scan pass 1

// Scratch (static __device__ — no allocation allowed)
__device__ float g_dinv[NN];
__device__ int   g_deg[NN];              // in-degree (without self loop)
__device__ int   g_start[NN];            // CSR offsets (exclusive scan of deg)
__device__ int   g_cursor[NN];           // fill cursors
__device__ int   g_src[EE];              // CSR: source rows grouped by target
__device__ float g_g1[NN * 12];          // (x@W1)*dinv
__device__ float g_u[NN * 12];           // relu(layer1)*dinv (pre-W2 low-rank form)
__device__ int4  g_edges4[(EE + 1) / 2]; // packed int32 edges {r0,c0,r1,c1}
__device__ int   g_bsum[NB1];
__device__ int   g_idx64;

// ---------------------------------------------------------------------------
__global__ void k_detect(const int* ei) {
    if (blockIdx.x == 0 && threadIdx.x == 0) {
        int acc = 0;
        #pragma unroll
        for (int i = 0; i < 32; ++i) acc |= ei[2 * i + 1];
        g_idx64 = (acc == 0) ? 1 : 0;
    }
}

__global__ void k_zero(int n) {
    int i = blockIdx.x * blockDim.x + threadIdx.x;
    if (i < n) g_deg[i] = 0;
}

// ---------------------------------------------------------------------------
// Convert edge index to packed int32 pairs + degree histogram (scalar int atomics).
__global__ void k_deg_convert(const void* __restrict__ ei, int ecnt) {
    int t  = blockIdx.x * blockDim.x + threadIdx.x;
    int e0 = t * 2;
    if (e0 >= ecnt) return;
    bool two = (e0 + 1 < ecnt);
    int r0, c0, r1 = 0, c1 = 0;
    if (g_idx64) {
        const long long* p = (const long long*)ei;
        r0 = (int)p[e0];
        c0 = (int)p[(long long)ecnt + e0];
        if (two) { r1 = (int)p[e0 + 1]; c1 = (int)p[(long long)ecnt + e0 + 1]; }
    } else {
        const int* p = (const int*)ei;
        r0 = p[e0];
        c0 = p[ecnt + e0];
        if (two) { r1 = p[e0 + 1]; c1 = p[ecnt + e0 + 1]; }
    }
    g_edges4[t] = make_int4(r0, c0, r1, c1);
    atomicAdd(&g_deg[c0], 1);
    if (two) atomicAdd(&g_deg[c1], 1);
}

// ---------------------------------------------------------------------------
// Exclusive scan of g_deg -> g_start (3 kernels)
__global__ void k_scan1(int n) {
    __shared__ int ts[SCAN_T];
    int base = blockIdx.x * SCAN_CHUNK + threadIdx.x * SCAN_E;
    int v[SCAN_E];
    int sum = 0;
    #pragma unroll
    for (int j = 0; j < SCAN_E; ++j) {
        int idx = base + j;
        v[j] = (idx < n) ? g_deg[idx] : 0;
        sum += v[j];
    }
    ts[threadIdx.x] = sum;
    __syncthreads();
    for (int off = 1; off < SCAN_T; off <<= 1) {
        int t = (threadIdx.x >= off) ? ts[threadIdx.x - off] : 0;
        __syncthreads();
        ts[threadIdx.x] += t;
        __syncthreads();
    }
    int run = ts[threadIdx.x] - sum;  // exclusive prefix of this thread
    if (threadIdx.x == SCAN_T - 1) g_bsum[blockIdx.x] = ts[SCAN_T - 1];
    #pragma unroll
    for (int j = 0; j < SCAN_E; ++j) {
        int idx = base + j;
        if (idx < n) g_start[idx] = run;
        run += v[j];
    }
}

__global__ void k_scan2() {
    if (threadIdx.x == 0 && blockIdx.x == 0) {
        int run = 0;
        for (int b = 0; b < NB1; ++b) {
            int t = g_bsum[b];
            g_bsum[b] = run;
            run += t;
        }
    }
}

__global__ void k_scan3(int n) {
    int i = blockIdx.x * blockDim.x + threadIdx.x;
    if (i >= n) return;
    int s = g_start[i] + g_bsum[i / SCAN_CHUNK];
    g_start[i]  = s;
    g_cursor[i] = s;
    g_dinv[i]   = rsqrtf((float)(g_deg[i] + 1));   // +1: self loop
}

// ---------------------------------------------------------------------------
// CSR fill: slot = cursor[col]++ ; src[slot] = row
__global__ void k_fill(int ecnt) {
    int t  = blockIdx.x * blockDim.x + threadIdx.x;
    int e0 = t * 2;
    if (e0 >= ecnt) return;
    int4 rc = __ldg(&g_edges4[t]);
    int s0 = atomicAdd(&g_cursor[rc.y], 1);
    g_src[s0] = rc.x;
    if (e0 + 1 < ecnt) {
        int s1 = atomicAdd(&g_cursor[rc.w], 1);
        g_src[s1] = rc.z;
    }
}

// ---------------------------------------------------------------------------
// GEMM1: g1[n][j] = dinv[n] * sum_k x[n][k] * W1[k][j]   (128 -> 12)
__device__ __forceinline__ float comp4(const float4& v, int kk) {
    return kk == 0 ? v.x : kk == 1 ? v.y : kk == 2 ? v.z : v.w;
}

__global__ void k_gemm1(const float* __restrict__ x, const float* __restrict__ W1, int n) {
    __shared__ float Ws[FIN * 12];
    for (int i = threadIdx.x; i < FIN * 12; i += blockDim.x) Ws[i] = W1[i];
    __syncthreads();

    int g  = blockIdx.x * blockDim.x + threadIdx.x;
    int n0 = g * 2;
    if (n0 >= n) return;
    bool two = (n0 + 1 < n);

    float acc0[12], acc1v[12];
    #pragma unroll
    for (int j = 0; j < 12; ++j) { acc0[j] = 0.0f; acc1v[j] = 0.0f; }

    const float4* xr0 = (const float4*)x + (size_t)n0 * (FIN / 4);
    const float4* xr1 = xr0 + (FIN / 4);

    #pragma unroll 4
    for (int k4 = 0; k4 < FIN / 4; ++k4) {
        float4 a = __ldcs(xr0 + k4);
        float4 b = two ? __ldcs(xr1 + k4) : make_float4(0.f, 0.f, 0.f, 0.f);
        #pragma unroll
        for (int kk = 0; kk < 4; ++kk) {
            const float4* wp = (const float4*)(Ws + (k4 * 4 + kk) * 12);
            float4 w0 = wp[0], w1 = wp[1], w2 = wp[2];
            float xa = comp4(a, kk);
            float xb = comp4(b, kk);
            acc0[0]  += xa * w0.x; acc0[1]  += xa * w0.y; acc0[2]  += xa * w0.z; acc0[3]  += xa * w0.w;
            acc0[4]  += xa * w1.x; acc0[5]  += xa * w1.y; acc0[6]  += xa * w1.z; acc0[7]  += xa * w1.w;
            acc0[8]  += xa * w2.x; acc0[9]  += xa * w2.y; acc0[10] += xa * w2.z; acc0[11] += xa * w2.w;
            acc1v[0]  += xb * w0.x; acc1v[1]  += xb * w0.y; acc1v[2]  += xb * w0.z; acc1v[3]  += xb * w0.w;
            acc1v[4]  += xb * w1.x; acc1v[5]  += xb * w1.y; acc1v[6]  += xb * w1.z; acc1v[7]  += xb * w1.w;
            acc1v[8]  += xb * w2.x; acc1v[9]  += xb * w2.y; acc1v[10] += xb * w2.z; acc1v[11] += xb * w2.w;
        }
    }

    {
        float dn = g_dinv[n0];
        float4* out4 = (float4*)g_g1 + (size_t)n0 * 3;
        out4[0] = make_float4(acc0[0] * dn, acc0[1] * dn, acc0[2]  * dn, acc0[3]  * dn);
        out4[1] = make_float4(acc0[4] * dn, acc0[5] * dn, acc0[6]  * dn, acc0[7]  * dn);
        out4[2] = make_float4(acc0[8] * dn, acc0[9] * dn, acc0[10] * dn, acc0[11] * dn);
    }
    if (two) {
        float dn = g_dinv[n0 + 1];
        float4* out4 = (float4*)g_g1 + (size_t)(n0 + 1) * 3;
        out4[0] = make_float4(acc1v[0] * dn, acc1v[1] * dn, acc1v[2]  * dn, acc1v[3]  * dn);
        out4[1] = make_float4(acc1v[4] * dn, acc1v[5] * dn, acc1v[6]  * dn, acc1v[7]  * dn);
        out4[2] = make_float4(acc1v[8] * dn, acc1v[9] * dn, acc1v[10] * dn, acc1v[11] * dn);
    }
}

// ---------------------------------------------------------------------------
__device__ __forceinline__ void f4acc(float4& a, const float4& b) {
    a.x += b.x; a.y += b.y; a.z += b.z; a.w += b.w;
}

// Gather layer 1 + epilogue: u = relu(dinv*(sum_in g1 + g1[self]) + b1) * dinv
__global__ void k_gather_u(const float* __restrict__ b1v, int n) {
    __shared__ float bs[12];
    if (threadIdx.x < 12) bs[threadIdx.x] = b1v[threadIdx.x];
    __syncthreads();

    int node = blockIdx.x * blockDim.x + threadIdx.x;
    if (node >= n) return;
    int s = g_start[node];
    int e = s + g_deg[node];

    const float4* self = (const float4*)g_g1 + (size_t)node * 3;
    float4 a0 = self[0], a1 = self[1], a2 = self[2];

    int i = s;
    for (; i + 1 < e; i += 2) {
        int r0 = __ldg(&g_src[i]);
        int r1 = __ldg(&g_src[i + 1]);
        const float4* p0 = (const float4*)g_g1 + (size_t)r0 * 3;
        const float4* p1 = (const float4*)g_g1 + (size_t)r1 * 3;
        float4 x0 = __ldg(p0), x1 = __ldg(p0 + 1), x2 = __ldg(p0 + 2);
        float4 y0 = __ldg(p1), y1 = __ldg(p1 + 1), y2 = __ldg(p1 + 2);
        f4acc(a0, x0); f4acc(a1, x1); f4acc(a2, x2);
        f4acc(a0, y0); f4acc(a1, y1); f4acc(a2, y2);
    }
    if (i < e) {
        int r0 = __ldg(&g_src[i]);
        const float4* p0 = (const float4*)g_g1 + (size_t)r0 * 3;
        f4acc(a0, __ldg(p0)); f4acc(a1, __ldg(p0 + 1)); f4acc(a2, __ldg(p0 + 2));
    }

    float dn = g_dinv[node];
    float4* out4 = (float4*)g_u + (size_t)node * 3;
    float4 r;
    r.x = fmaxf(dn * a0.x + bs[0],  0.0f) * dn;
    r.y = fmaxf(dn * a0.y + bs[1],  0.0f) * dn;
    r.z = fmaxf(dn * a0.z + bs[2],  0.0f) * dn;
    r.w = fmaxf(dn * a0.w + bs[3],  0.0f) * dn;
    out4[0] = r;
    r.x = fmaxf(dn * a1.x + bs[4],  0.0f) * dn;
    r.y = fmaxf(dn * a1.y + bs[5],  0.0f) * dn;
    r.z = fmaxf(dn * a1.z + bs[6],  0.0f) * dn;
    r.w = fmaxf(dn * a1.w + bs[7],  0.0f) * dn;
    out4[1] = r;
    r.x = fmaxf(dn * a2.x + bs[8],  0.0f) * dn;
    r.y = fmaxf(dn * a2.y + bs[9],  0.0f) * dn;
    r.z = fmaxf(dn * a2.z + bs[10], 0.0f) * dn;
    r.w = fmaxf(dn * a2.w + bs[11], 0.0f) * dn;
    out4[2] = r;
}

// ---------------------------------------------------------------------------
// Gather layer 2 + full MLP epilogue:
// v = dinv*(sum_in u + u[self]); h2 = relu(v@W2+b2); h3 = relu(h2@Wf1+bf1); out = h3@Wf2+bf2
__global__ void k_gather_final(const float* __restrict__ W2, const float* __restrict__ b2v,
                               const float* __restrict__ Wf1, const float* __restrict__ bf1,
                               const float* __restrict__ Wf2, const float* __restrict__ bf2,
                               float* __restrict__ out, int n) {
    __shared__ float W2s[12 * 24];
    __shared__ float Wf1s[24 * 32];
    __shared__ float Wf2s[32 * 2];
    __shared__ float b2s[24], bf1s[32], bf2s[2];
    for (int i = threadIdx.x; i < 12 * 24; i += blockDim.x) W2s[i] = W2[i];
    for (int i = threadIdx.x; i < 24 * 32; i += blockDim.x) Wf1s[i] = Wf1[i];
    if (threadIdx.x < 64) Wf2s[threadIdx.x] = Wf2[threadIdx.x];
    if (threadIdx.x < 24) b2s[threadIdx.x] = b2v[threadIdx.x];
    if (threadIdx.x < 32) bf1s[threadIdx.x] = bf1[threadIdx.x];
    if (threadIdx.x < 2)  bf2s[threadIdx.x] = bf2[threadIdx.x];
    __syncthreads();

    int node = blockIdx.x * blockDim.x + threadIdx.x;
    if (node >= n) return;
    int s = g_start[node];
    int e = s + g_deg[node];

    const float4* self = (const float4*)g_u + (size_t)node * 3;
    float4 a0 = self[0], a1 = self[1], a2 = self[2];

    int i = s;
    for (; i + 1 < e; i += 2) {
        int r0 = __ldg(&g_src[i]);
        int r1 = __ldg(&g_src[i + 1]);
        const float4* p0 = (const float4*)g_u + (size_t)r0 * 3;
        const float4* p1 = (const float4*)g_u + (size_t)r1 * 3;
        float4 x0 = __ldg(p0), x1 = __ldg(p0 + 1), x2 = __ldg(p0 + 2);
        float4 y0 = __ldg(p1), y1 = __ldg(p1 + 1), y2 = __ldg(p1 + 2);
        f4acc(a0, x0); f4acc(a1, x1); f4acc(a2, x2);
        f4acc(a0, y0); f4acc(a1, y1); f4acc(a2, y2);
    }
    if (i < e) {
        int r0 = __ldg(&g_src[i]);
        const float4* p0 = (const float4*)g_u + (size_t)r0 * 3;
        f4acc(a0, __ldg(p0)); f4acc(a1, __ldg(p0 + 1)); f4acc(a2, __ldg(p0 + 2));
    }

    float dn = g_dinv[node];
    float v[12] = {
        dn * a0.x, dn * a0.y, dn * a0.z, dn * a0.w,
        dn * a1.x, dn * a1.y, dn * a1.z, dn * a1.w,
        dn * a2.x, dn * a2.y, dn * a2.z, dn * a2.w
    };

    float h2[24];
    #pragma unroll
    for (int j2 = 0; j2 < 24; ++j2) h2[j2] = b2s[j2];
    #pragma unroll
    for (int j = 0; j < 12; ++j) {
        float hv = v[j];
        const float* wr = W2s + j * 24;
        #pragma unroll
        for (int j2 = 0; j2 < 24; ++j2) h2[j2] += hv * wr[j2];
    }
    #pragma unroll
    for (int j2 = 0; j2 < 24; ++j2) h2[j2] = fmaxf(h2[j2], 0.0f);

    float h3[32];
    #pragma unroll
    for (int o = 0; o < 32; ++o) h3[o] = bf1s[o];
    #pragma unroll
    for (int j = 0; j < 24; ++j) {
        float hv = h2[j];
        const float* wr = Wf1s + j * 32;
        #pragma unroll
        for (int o = 0; o < 32; ++o) h3[o] += hv * wr[o];
    }
    #pragma unroll
    for (int o = 0; o < 32; ++o) h3[o] = fmaxf(h3[o], 0.0f);

    float o0 = bf2s[0], o1 = bf2s[1];
    #pragma unroll
    for (int o = 0; o < 32; ++o) {
        o0 += h3[o] * Wf2s[o * 2 + 0];
        o1 += h3[o] * Wf2s[o * 2 + 1];
    }
    ((float2*)out)[node] = make_float2(o0, o1);
}

// ---------------------------------------------------------------------------
extern "C" void kernel_launch(void* const* d_in, const int* in_sizes, int n_in,
                              void* d_out, int out_size) {
    const float* x   = (const float*)d_in[0];
    const void*  ei  = d_in[1];
    const float* W1  = (const float*)d_in[2];
    const float* b1  = (const float*)d_in[3];
    const float* W2  = (const float*)d_in[4];
    const float* b2  = (const float*)d_in[5];
    const float* Wf1 = (const float*)d_in[6];
    const float* bf1 = (const float*)d_in[7];
    const float* Wf2 = (const float*)d_in[8];
    const float* bf2 = (const float*)d_in[9];
    float* out = (float*)d_out;

    const int n = in_sizes[0] / FIN;       // 200000
    const int e = in_sizes[1] / 2;         // 6400000
    const int epairs = (e + 1) / 2;

    const int T = 256;
    k_detect<<<1, 32>>>((const int*)ei);
    k_zero<<<(n + T - 1) / T, T>>>(n);
    k_deg_convert<<<(epairs + T - 1) / T, T>>>(ei, e);
    k_scan1<<<NB1, SCAN_T>>>(n);
    k_scan2<<<1, 32>>>();
    k_scan3<<<(n + T - 1) / T, T>>>(n);
    k_fill<<<(epairs + T - 1) / T, T>>>(e);
    k_gemm1<<<((n + 1) / 2 + T - 1) / T, T>>>(x, W1, n);
    k_gather_u<<<(n + T - 1) / T, T>>>(b1, n);
    k_gather_final<<<(n + T - 1) / T, T>>>(W2, b2, Wf1, bf1, Wf2, bf2, out, n);
}

// round 5
// speedup vs baseline: 1.5597x; 1.1183x over previous
#include <cuda_runtime.h>
#include <cuda_fp16.h>

#define NN 200000
#define EE 6400000
#define FIN 128

#define SCAN_T 256
#define SCAN_E 8
#define SCAN_CHUNK (SCAN_T * SCAN_E)                    // 2048
#define NB1 ((NN + SCAN_CHUNK - 1) / SCAN_CHUNK)        // blocks in scan pass 1

// Scratch (static __device__ — no allocation allowed)
__device__ float g_dinv[NN];
__device__ int   g_deg[NN];
__device__ int   g_start[NN];
__device__ int   g_cursor[NN];
__device__ int   g_src[EE];
__device__ uint4 g_g1h[NN * 2];          // fp16 (x@W1)*dinv, 12 halves + 4 pad per node (32B)
__device__ uint4 g_uh[NN * 2];           // fp16 relu(layer1)*dinv, same layout
__device__ int4  g_edges4[(EE + 1) / 2]; // packed int32 edges {r0,c0,r1,c1}
__device__ int   g_bsum[NB1];
__device__ int   g_idx64;

// ---------------------------------------------------------------------------
__device__ __forceinline__ unsigned pack2(float a, float b) {
    __half2 h = __floats2half2_rn(a, b);
    return *reinterpret_cast<unsigned*>(&h);
}
__device__ __forceinline__ void add2(float& a, float& b, unsigned u) {
    __half2 h = *reinterpret_cast<__half2*>(&u);
    float2 f = __half22float2(h);
    a += f.x; b += f.y;
}
__device__ __forceinline__ void acc12(float* acc, uint4 A, uint4 B) {
    add2(acc[0],  acc[1],  A.x);
    add2(acc[2],  acc[3],  A.y);
    add2(acc[4],  acc[5],  A.z);
    add2(acc[6],  acc[7],  A.w);
    add2(acc[8],  acc[9],  B.x);
    add2(acc[10], acc[11], B.y);
}

// ---------------------------------------------------------------------------
// Zero degrees + detect edge-index dtype (int64 -> odd 32-bit words all zero)
__global__ void k_zero_detect(const int* ei, int n) {
    int i = blockIdx.x * blockDim.x + threadIdx.x;
    if (i < n) g_deg[i] = 0;
    if (i == 0) {
        int acc = 0;
        #pragma unroll
        for (int j = 0; j < 32; ++j) acc |= ei[2 * j + 1];
        g_idx64 = (acc == 0) ? 1 : 0;
    }
}

// ---------------------------------------------------------------------------
// Convert edge index to packed int32 pairs + degree histogram.
__global__ void k_deg_convert(const void* __restrict__ ei, int ecnt) {
    int t  = blockIdx.x * blockDim.x + threadIdx.x;
    int e0 = t * 2;
    if (e0 >= ecnt) return;
    bool two = (e0 + 1 < ecnt);
    int r0, c0, r1 = 0, c1 = 0;
    if (g_idx64) {
        const long long* p = (const long long*)ei;
        r0 = (int)p[e0];
        c0 = (int)p[(long long)ecnt + e0];
        if (two) { r1 = (int)p[e0 + 1]; c1 = (int)p[(long long)ecnt + e0 + 1]; }
    } else {
        const int* p = (const int*)ei;
        r0 = p[e0];
        c0 = p[ecnt + e0];
        if (two) { r1 = p[e0 + 1]; c1 = p[ecnt + e0 + 1]; }
    }
    g_edges4[t] = make_int4(r0, c0, r1, c1);
    atomicAdd(&g_deg[c0], 1);
    if (two) atomicAdd(&g_deg[c1], 1);
}

// ---------------------------------------------------------------------------
// Exclusive scan of g_deg -> g_start (3 kernels)
__global__ void k_scan1(int n) {
    __shared__ int ts[SCAN_T];
    int base = blockIdx.x * SCAN_CHUNK + threadIdx.x * SCAN_E;
    int v[SCAN_E];
    int sum = 0;
    #pragma unroll
    for (int j = 0; j < SCAN_E; ++j) {
        int idx = base + j;
        v[j] = (idx < n) ? g_deg[idx] : 0;
        sum += v[j];
    }
    ts[threadIdx.x] = sum;
    __syncthreads();
    for (int off = 1; off < SCAN_T; off <<= 1) {
        int t = (threadIdx.x >= off) ? ts[threadIdx.x - off] : 0;
        __syncthreads();
        ts[threadIdx.x] += t;
        __syncthreads();
    }
    int run = ts[threadIdx.x] - sum;
    if (threadIdx.x == SCAN_T - 1) g_bsum[blockIdx.x] = ts[SCAN_T - 1];
    #pragma unroll
    for (int j = 0; j < SCAN_E; ++j) {
        int idx = base + j;
        if (idx < n) g_start[idx] = run;
        run += v[j];
    }
}

__global__ void k_scan2() {
    if (threadIdx.x == 0 && blockIdx.x == 0) {
        int run = 0;
        for (int b = 0; b < NB1; ++b) {
            int t = g_bsum[b];
            g_bsum[b] = run;
            run += t;
        }
    }
}

__global__ void k_scan3(int n) {
    int i = blockIdx.x * blockDim.x + threadIdx.x;
    if (i >= n) return;
    int s = g_start[i] + g_bsum[i / SCAN_CHUNK];
    g_start[i]  = s;
    g_cursor[i] = s;
    g_dinv[i]   = rsqrtf((float)(g_deg[i] + 1));
}

// ---------------------------------------------------------------------------
// CSR fill: slot = cursor[col]++ ; src[slot] = row
__global__ void k_fill(int ecnt) {
    int t  = blockIdx.x * blockDim.x + threadIdx.x;
    int e0 = t * 2;
    if (e0 >= ecnt) return;
    int4 rc = __ldg(&g_edges4[t]);
    int s0 = atomicAdd(&g_cursor[rc.y], 1);
    g_src[s0] = rc.x;
    if (e0 + 1 < ecnt) {
        int s1 = atomicAdd(&g_cursor[rc.w], 1);
        g_src[s1] = rc.z;
    }
}

// ---------------------------------------------------------------------------
// GEMM1: g1h[n] = fp16( dinv[n] * (x[n] @ W1) )   (128 -> 12)
__device__ __forceinline__ float comp4(const float4& v, int kk) {
    return kk == 0 ? v.x : kk == 1 ? v.y : kk == 2 ? v.z : v.w;
}

__global__ void k_gemm1(const float* __restrict__ x, const float* __restrict__ W1, int n) {
    __shared__ float Ws[FIN * 12];
    for (int i = threadIdx.x; i < FIN * 12; i += blockDim.x) Ws[i] = W1[i];
    __syncthreads();

    int g  = blockIdx.x * blockDim.x + threadIdx.x;
    int n0 = g * 2;
    if (n0 >= n) return;
    bool two = (n0 + 1 < n);

    float a0[12], a1v[12];
    #pragma unroll
    for (int j = 0; j < 12; ++j) { a0[j] = 0.0f; a1v[j] = 0.0f; }

    const float4* xr0 = (const float4*)x + (size_t)n0 * (FIN / 4);
    const float4* xr1 = xr0 + (FIN / 4);

    #pragma unroll 4
    for (int k4 = 0; k4 < FIN / 4; ++k4) {
        float4 a = __ldcs(xr0 + k4);
        float4 b = two ? __ldcs(xr1 + k4) : make_float4(0.f, 0.f, 0.f, 0.f);
        #pragma unroll
        for (int kk = 0; kk < 4; ++kk) {
            const float4* wp = (const float4*)(Ws + (k4 * 4 + kk) * 12);
            float4 w0 = wp[0], w1 = wp[1], w2 = wp[2];
            float xa = comp4(a, kk);
            float xb = comp4(b, kk);
            a0[0]  += xa * w0.x; a0[1]  += xa * w0.y; a0[2]  += xa * w0.z; a0[3]  += xa * w0.w;
            a0[4]  += xa * w1.x; a0[5]  += xa * w1.y; a0[6]  += xa * w1.z; a0[7]  += xa * w1.w;
            a0[8]  += xa * w2.x; a0[9]  += xa * w2.y; a0[10] += xa * w2.z; a0[11] += xa * w2.w;
            a1v[0]  += xb * w0.x; a1v[1]  += xb * w0.y; a1v[2]  += xb * w0.z; a1v[3]  += xb * w0.w;
            a1v[4]  += xb * w1.x; a1v[5]  += xb * w1.y; a1v[6]  += xb * w1.z; a1v[7]  += xb * w1.w;
            a1v[8]  += xb * w2.x; a1v[9]  += xb * w2.y; a1v[10] += xb * w2.z; a1v[11] += xb * w2.w;
        }
    }

    {
        float dn = g_dinv[n0];
        uint4 A, B;
        A.x = pack2(a0[0] * dn, a0[1] * dn);
        A.y = pack2(a0[2] * dn, a0[3] * dn);
        A.z = pack2(a0[4] * dn, a0[5] * dn);
        A.w = pack2(a0[6] * dn, a0[7] * dn);
        B.x = pack2(a0[8] * dn, a0[9] * dn);
        B.y = pack2(a0[10] * dn, a0[11] * dn);
        B.z = 0; B.w = 0;
        g_g1h[(size_t)n0 * 2]     = A;
        g_g1h[(size_t)n0 * 2 + 1] = B;
    }
    if (two) {
        float dn = g_dinv[n0 + 1];
        uint4 A, B;
        A.x = pack2(a1v[0] * dn, a1v[1] * dn);
        A.y = pack2(a1v[2] * dn, a1v[3] * dn);
        A.z = pack2(a1v[4] * dn, a1v[5] * dn);
        A.w = pack2(a1v[6] * dn, a1v[7] * dn);
        B.x = pack2(a1v[8] * dn, a1v[9] * dn);
        B.y = pack2(a1v[10] * dn, a1v[11] * dn);
        B.z = 0; B.w = 0;
        g_g1h[(size_t)(n0 + 1) * 2]     = A;
        g_g1h[(size_t)(n0 + 1) * 2 + 1] = B;
    }
}

// ---------------------------------------------------------------------------
// Shared gather core: sums self + in-neighbors of `node` from feat (fp16 32B slots)
__device__ __forceinline__ void gather12(const uint4* __restrict__ feat, int node,
                                         float* acc) {
    int s = g_start[node];
    int e = s + g_deg[node];

    uint4 SA = feat[(size_t)node * 2];
    uint4 SB = feat[(size_t)node * 2 + 1];
    #pragma unroll
    for (int j = 0; j < 12; ++j) acc[j] = 0.0f;
    acc12(acc, SA, SB);

    int i = s;
    for (; i + 3 < e; i += 4) {
        int r0 = __ldg(&g_src[i]);
        int r1 = __ldg(&g_src[i + 1]);
        int r2 = __ldg(&g_src[i + 2]);
        int r3 = __ldg(&g_src[i + 3]);
        uint4 A0 = __ldg(feat + (size_t)r0 * 2), B0 = __ldg(feat + (size_t)r0 * 2 + 1);
        uint4 A1 = __ldg(feat + (size_t)r1 * 2), B1 = __ldg(feat + (size_t)r1 * 2 + 1);
        uint4 A2 = __ldg(feat + (size_t)r2 * 2), B2 = __ldg(feat + (size_t)r2 * 2 + 1);
        uint4 A3 = __ldg(feat + (size_t)r3 * 2), B3 = __ldg(feat + (size_t)r3 * 2 + 1);
        acc12(acc, A0, B0);
        acc12(acc, A1, B1);
        acc12(acc, A2, B2);
        acc12(acc, A3, B3);
    }
    for (; i < e; ++i) {
        int r0 = __ldg(&g_src[i]);
        uint4 A0 = __ldg(feat + (size_t)r0 * 2), B0 = __ldg(feat + (size_t)r0 * 2 + 1);
        acc12(acc, A0, B0);
    }
}

// Gather layer 1 + epilogue: u = fp16( relu(dinv*sum + b1) * dinv )
__global__ void k_gather_u(const float* __restrict__ b1v, int n) {
    __shared__ float bs[12];
    if (threadIdx.x < 12) bs[threadIdx.x] = b1v[threadIdx.x];
    __syncthreads();

    int node = blockIdx.x * blockDim.x + threadIdx.x;
    if (node >= n) return;

    float acc[12];
    gather12(g_g1h, node, acc);

    float dn = g_dinv[node];
    float u[12];
    #pragma unroll
    for (int j = 0; j < 12; ++j)
        u[j] = fmaxf(dn * acc[j] + bs[j], 0.0f) * dn;

    uint4 A, B;
    A.x = pack2(u[0], u[1]);
    A.y = pack2(u[2], u[3]);
    A.z = pack2(u[4], u[5]);
    A.w = pack2(u[6], u[7]);
    B.x = pack2(u[8], u[9]);
    B.y = pack2(u[10], u[11]);
    B.z = 0; B.w = 0;
    g_uh[(size_t)node * 2]     = A;
    g_uh[(size_t)node * 2 + 1] = B;
}

// ---------------------------------------------------------------------------
// Gather layer 2 + MLP epilogue.
__global__ void k_gather_final(const float* __restrict__ W2, const float* __restrict__ b2v,
                               const float* __restrict__ Wf1, const float* __restrict__ bf1,
                               const float* __restrict__ Wf2, const float* __restrict__ bf2,
                               float* __restrict__ out, int n) {
    __shared__ float W2s[12 * 24];
    __shared__ float Wf1s[24 * 32];
    __shared__ float Wf2s[32 * 2];
    __shared__ float b2s[24], bf1s[32], bf2s[2];
    for (int i = threadIdx.x; i < 12 * 24; i += blockDim.x) W2s[i] = W2[i];
    for (int i = threadIdx.x; i < 24 * 32; i += blockDim.x) Wf1s[i] = Wf1[i];
    if (threadIdx.x < 64) Wf2s[threadIdx.x] = Wf2[threadIdx.x];
    if (threadIdx.x < 24) b2s[threadIdx.x] = b2v[threadIdx.x];
    if (threadIdx.x < 32) bf1s[threadIdx.x] = bf1[threadIdx.x];
    if (threadIdx.x < 2)  bf2s[threadIdx.x] = bf2[threadIdx.x];
    __syncthreads();

    int node = blockIdx.x * blockDim.x + threadIdx.x;
    if (node >= n) return;

    float acc[12];
    gather12(g_uh, node, acc);

    float dn = g_dinv[node];
    float v[12];
    #pragma unroll
    for (int j = 0; j < 12; ++j) v[j] = dn * acc[j];

    float h2[24];
    #pragma unroll
    for (int j2 = 0; j2 < 24; ++j2) h2[j2] = b2s[j2];
    #pragma unroll
    for (int j = 0; j < 12; ++j) {
        float hv = v[j];
        const float* wr = W2s + j * 24;
        #pragma unroll
        for (int j2 = 0; j2 < 24; ++j2) h2[j2] += hv * wr[j2];
    }
    #pragma unroll
    for (int j2 = 0; j2 < 24; ++j2) h2[j2] = fmaxf(h2[j2], 0.0f);

    float h3[32];
    #pragma unroll
    for (int o = 0; o < 32; ++o) h3[o] = bf1s[o];
    #pragma unroll
    for (int j = 0; j < 24; ++j) {
        float hv = h2[j];
        const float* wr = Wf1s + j * 32;
        #pragma unroll
        for (int o = 0; o < 32; ++o) h3[o] += hv * wr[o];
    }
    #pragma unroll
    for (int o = 0; o < 32; ++o) h3[o] = fmaxf(h3[o], 0.0f);

    float o0 = bf2s[0], o1 = bf2s[1];
    #pragma unroll
    for (int o = 0; o < 32; ++o) {
        o0 += h3[o] * Wf2s[o * 2 + 0];
        o1 += h3[o] * Wf2s[o * 2 + 1];
    }
    ((float2*)out)[node] = make_float2(o0, o1);
}

// ---------------------------------------------------------------------------
extern "C" void kernel_launch(void* const* d_in, const int* in_sizes, int n_in,
                              void* d_out, int out_size) {
    const float* x   = (const float*)d_in[0];
    const void*  ei  = d_in[1];
    const float* W1  = (const float*)d_in[2];
    const float* b1  = (const float*)d_in[3];
    const float* W2  = (const float*)d_in[4];
    const float* b2  = (const float*)d_in[5];
    const float* Wf1 = (const float*)d_in[6];
    const float* bf1 = (const float*)d_in[7];
    const float* Wf2 = (const float*)d_in[8];
    const float* bf2 = (const float*)d_in[9];
    float* out = (float*)d_out;

    const int n = in_sizes[0] / FIN;       // 200000
    const int e = in_sizes[1] / 2;         // 6400000
    const int epairs = (e + 1) / 2;

    const int T = 256;
    k_zero_detect<<<(n + T - 1) / T, T>>>((const int*)ei, n);
    k_deg_convert<<<(epairs + T - 1) / T, T>>>(ei, e);
    k_scan1<<<NB1, SCAN_T>>>(n);
    k_scan2<<<1, 32>>>();
    k_scan3<<<(n + T - 1) / T, T>>>(n);
    k_fill<<<(epairs + T - 1) / T, T>>>(e);
    k_gemm1<<<((n + 1) / 2 + T - 1) / T, T>>>(x, W1, n);
    k_gather_u<<<(n + T - 1) / T, T>>>(b1, n);
    k_gather_final<<<(n + T - 1) / T, T>>>(W2, b2, Wf1, bf1, Wf2, bf2, out, n);
}

// round 7
// speedup vs baseline: 1.6344x; 1.0479x over previous
#include <cuda_runtime.h>
#include <cuda_fp16.h>

#define NN 200000
#define EE 6400000
#define FIN 128

#define SCAN_T 256
#define SCAN_E 8
#define SCAN_CHUNK (SCAN_T * SCAN_E)                    // 2048
#define NB1 ((NN + SCAN_CHUNK - 1) / SCAN_CHUNK)        // 98

// Scratch (static __device__ — no allocation allowed)
__device__ float g_dinv[NN];
__device__ int   g_deg[NN];
__device__ int   g_start[NN];
__device__ int   g_cursor[NN];
__device__ int   g_src[EE];
__device__ uint4 g_g1h[NN * 2];          // fp16 (x@W1)*dinv, 12 halves + 4 pad (32B/node)
__device__ uint4 g_uh[NN * 2];           // fp16 relu(layer1)*dinv, same layout
__device__ float g_v[NN * 12];           // fp32 layer-2 aggregate (pre-MLP)
__device__ int4  g_edges4[(EE + 3) / 4 * 2]; // packed int32 edges {r,c} pairs
__device__ int   g_bsum[NB1];
__device__ int   g_idx64;

// ---------------------------------------------------------------------------
__device__ __forceinline__ unsigned pack2(float a, float b) {
    __half2 h = __floats2half2_rn(a, b);
    return *reinterpret_cast<unsigned*>(&h);
}
__device__ __forceinline__ void add2(float& a, float& b, unsigned u) {
    __half2 h = *reinterpret_cast<__half2*>(&u);
    float2 f = __half22float2(h);
    a += f.x; b += f.y;
}
__device__ __forceinline__ void acc12(float* acc, uint4 A, uint4 B) {
    add2(acc[0],  acc[1],  A.x);
    add2(acc[2],  acc[3],  A.y);
    add2(acc[4],  acc[5],  A.z);
    add2(acc[6],  acc[7],  A.w);
    add2(acc[8],  acc[9],  B.x);
    add2(acc[10], acc[11], B.y);
}

// ---------------------------------------------------------------------------
__global__ void k_zero_detect(const int* ei, int n) {
    int i = blockIdx.x * blockDim.x + threadIdx.x;
    if (i < n) g_deg[i] = 0;
    if (i == 0) {
        int acc = 0;
        #pragma unroll
        for (int j = 0; j < 32; ++j) acc |= ei[2 * j + 1];
        g_idx64 = (acc == 0) ? 1 : 0;
    }
}

// ---------------------------------------------------------------------------
// Convert edges to packed int32 pairs + degree histogram. 4 edges/thread.
__global__ void k_deg_convert(const void* __restrict__ ei, int ecnt) {
    int t  = blockIdx.x * blockDim.x + threadIdx.x;
    int e0 = t * 4;
    if (e0 >= ecnt) return;
    int r[4], c[4];
    if (e0 + 3 < ecnt) {
        if (g_idx64) {
            const longlong2* pr = (const longlong2*)((const long long*)ei + e0);
            const longlong2* pc = (const longlong2*)((const long long*)ei + ecnt + e0);
            longlong2 r01 = __ldcs(pr), r23 = __ldcs(pr + 1);
            longlong2 c01 = __ldcs(pc), c23 = __ldcs(pc + 1);
            r[0] = (int)r01.x; r[1] = (int)r01.y; r[2] = (int)r23.x; r[3] = (int)r23.y;
            c[0] = (int)c01.x; c[1] = (int)c01.y; c[2] = (int)c23.x; c[3] = (int)c23.y;
        } else {
            const int4* pr = (const int4*)((const int*)ei + e0);
            const int4* pc = (const int4*)((const int*)ei + ecnt + e0);
            int4 rv = __ldcs(pr), cv = __ldcs(pc);
            r[0] = rv.x; r[1] = rv.y; r[2] = rv.z; r[3] = rv.w;
            c[0] = cv.x; c[1] = cv.y; c[2] = cv.z; c[3] = cv.w;
        }
        g_edges4[t * 2]     = make_int4(r[0], c[0], r[1], c[1]);
        g_edges4[t * 2 + 1] = make_int4(r[2], c[2], r[3], c[3]);
        atomicAdd(&g_deg[c[0]], 1);
        atomicAdd(&g_deg[c[1]], 1);
        atomicAdd(&g_deg[c[2]], 1);
        atomicAdd(&g_deg[c[3]], 1);
    } else {
        for (int k = 0; k < 4; ++k) {
            int e = e0 + k;
            int rr = 0, cc = 0;
            if (e < ecnt) {
                if (g_idx64) {
                    const long long* p = (const long long*)ei;
                    rr = (int)p[e]; cc = (int)p[(long long)ecnt + e];
                } else {
                    const int* p = (const int*)ei;
                    rr = p[e]; cc = p[ecnt + e];
                }
                atomicAdd(&g_deg[cc], 1);
            }
            ((int2*)g_edges4)[t * 4 + k] = make_int2(rr, cc);
        }
    }
}

// ---------------------------------------------------------------------------
// Exclusive scan of g_deg -> g_start
__global__ void k_scan1(int n) {
    __shared__ int ts[SCAN_T];
    int base = blockIdx.x * SCAN_CHUNK + threadIdx.x * SCAN_E;
    int v[SCAN_E];
    int sum = 0;
    #pragma unroll
    for (int j = 0; j < SCAN_E; ++j) {
        int idx = base + j;
        v[j] = (idx < n) ? g_deg[idx] : 0;
        sum += v[j];
    }
    ts[threadIdx.x] = sum;
    __syncthreads();
    for (int off = 1; off < SCAN_T; off <<= 1) {
        int t = (threadIdx.x >= off) ? ts[threadIdx.x - off] : 0;
        __syncthreads();
        ts[threadIdx.x] += t;
        __syncthreads();
    }
    int run = ts[threadIdx.x] - sum;
    if (threadIdx.x == SCAN_T - 1) g_bsum[blockIdx.x] = ts[SCAN_T - 1];
    #pragma unroll
    for (int j = 0; j < SCAN_E; ++j) {
        int idx = base + j;
        if (idx < n) g_start[idx] = run;
        run += v[j];
    }
}

// Parallel scan of the 98 block sums (single block)
__global__ void k_scan2() {
    __shared__ int ts[128];
    int t = threadIdx.x;
    int v = (t < NB1) ? g_bsum[t] : 0;
    ts[t] = v;
    __syncthreads();
    for (int off = 1; off < 128; off <<= 1) {
        int w = (t >= off) ? ts[t - off] : 0;
        __syncthreads();
        ts[t] += w;
        __syncthreads();
    }
    if (t < NB1) g_bsum[t] = ts[t] - v;   // exclusive
}

__global__ void k_scan3(int n) {
    int i = blockIdx.x * blockDim.x + threadIdx.x;
    if (i >= n) return;
    int s = g_start[i] + g_bsum[i / SCAN_CHUNK];
    g_start[i]  = s;
    g_cursor[i] = s;
    g_dinv[i]   = rsqrtf((float)(g_deg[i] + 1));
}

// ---------------------------------------------------------------------------
// CSR fill: 4 edges/thread
__global__ void k_fill(int ecnt) {
    int t  = blockIdx.x * blockDim.x + threadIdx.x;
    int e0 = t * 4;
    if (e0 >= ecnt) return;
    int4 rc01 = __ldg(&g_edges4[t * 2]);
    int4 rc23 = __ldg(&g_edges4[t * 2 + 1]);
    {
        int s = atomicAdd(&g_cursor[rc01.y], 1);
        g_src[s] = rc01.x;
    }
    if (e0 + 1 < ecnt) { int s = atomicAdd(&g_cursor[rc01.w], 1); g_src[s] = rc01.z; }
    if (e0 + 2 < ecnt) { int s = atomicAdd(&g_cursor[rc23.y], 1); g_src[s] = rc23.x; }
    if (e0 + 3 < ecnt) { int s = atomicAdd(&g_cursor[rc23.w], 1); g_src[s] = rc23.z; }
}

// ---------------------------------------------------------------------------
// GEMM1: g1h[n] = fp16( dinv[n] * (x[n] @ W1) )
__device__ __forceinline__ float comp4(const float4& v, int kk) {
    return kk == 0 ? v.x : kk == 1 ? v.y : kk == 2 ? v.z : v.w;
}

__global__ void k_gemm1(const float* __restrict__ x, const float* __restrict__ W1, int n) {
    __shared__ float Ws[FIN * 12];
    for (int i = threadIdx.x; i < FIN * 12; i += blockDim.x) Ws[i] = W1[i];
    __syncthreads();

    int g  = blockIdx.x * blockDim.x + threadIdx.x;
    int n0 = g * 2;
    if (n0 >= n) return;
    bool two = (n0 + 1 < n);

    float a0[12], a1v[12];
    #pragma unroll
    for (int j = 0; j < 12; ++j) { a0[j] = 0.0f; a1v[j] = 0.0f; }

    const float4* xr0 = (const float4*)x + (size_t)n0 * (FIN / 4);
    const float4* xr1 = xr0 + (FIN / 4);

    #pragma unroll 4
    for (int k4 = 0; k4 < FIN / 4; ++k4) {
        float4 a = __ldcs(xr0 + k4);
        float4 b = two ? __ldcs(xr1 + k4) : make_float4(0.f, 0.f, 0.f, 0.f);
        #pragma unroll
        for (int kk = 0; kk < 4; ++kk) {
            const float4* wp = (const float4*)(Ws + (k4 * 4 + kk) * 12);
            float4 w0 = wp[0], w1 = wp[1], w2 = wp[2];
            float xa = comp4(a, kk);
            float xb = comp4(b, kk);
            a0[0]  += xa * w0.x; a0[1]  += xa * w0.y; a0[2]  += xa * w0.z; a0[3]  += xa * w0.w;
            a0[4]  += xa * w1.x; a0[5]  += xa * w1.y; a0[6]  += xa * w1.z; a0[7]  += xa * w1.w;
            a0[8]  += xa * w2.x; a0[9]  += xa * w2.y; a0[10] += xa * w2.z; a0[11] += xa * w2.w;
            a1v[0]  += xb * w0.x; a1v[1]  += xb * w0.y; a1v[2]  += xb * w0.z; a1v[3]  += xb * w0.w;
            a1v[4]  += xb * w1.x; a1v[5]  += xb * w1.y; a1v[6]  += xb * w1.z; a1v[7]  += xb * w1.w;
            a1v[8]  += xb * w2.x; a1v[9]  += xb * w2.y; a1v[10] += xb * w2.z; a1v[11] += xb * w2.w;
        }
    }

    {
        float dn = g_dinv[n0];
        uint4 A, B;
        A.x = pack2(a0[0] * dn, a0[1] * dn);
        A.y = pack2(a0[2] * dn, a0[3] * dn);
        A.z = pack2(a0[4] * dn, a0[5] * dn);
        A.w = pack2(a0[6] * dn, a0[7] * dn);
        B.x = pack2(a0[8] * dn, a0[9] * dn);
        B.y = pack2(a0[10] * dn, a0[11] * dn);
        B.z = 0; B.w = 0;
        g_g1h[(size_t)n0 * 2]     = A;
        g_g1h[(size_t)n0 * 2 + 1] = B;
    }
    if (two) {
        float dn = g_dinv[n0 + 1];
        uint4 A, B;
        A.x = pack2(a1v[0] * dn, a1v[1] * dn);
        A.y = pack2(a1v[2] * dn, a1v[3] * dn);
        A.z = pack2(a1v[4] * dn, a1v[5] * dn);
        A.w = pack2(a1v[6] * dn, a1v[7] * dn);
        B.x = pack2(a1v[8] * dn, a1v[9] * dn);
        B.y = pack2(a1v[10] * dn, a1v[11] * dn);
        B.z = 0; B.w = 0;
        g_g1h[(size_t)(n0 + 1) * 2]     = A;
        g_g1h[(size_t)(n0 + 1) * 2 + 1] = B;
    }
}

// ---------------------------------------------------------------------------
// 4-lane cooperative gather. All lanes stay active (clamped node, predicated
// writes) so shfl_xor stays converged. Returns reduced sum in acc (all lanes).
__device__ __forceinline__ void gather12_c4(const uint4* __restrict__ feat,
                                            int node, int lane, float* acc) {
    int s = g_start[node];
    int d = g_deg[node];

    #pragma unroll
    for (int j = 0; j < 12; ++j) acc[j] = 0.0f;

    for (int i = s + lane; i < s + d; i += 4) {
        int r = __ldg(&g_src[i]);
        uint4 A = __ldg(feat + (size_t)r * 2);
        uint4 B = __ldg(feat + (size_t)r * 2 + 1);
        acc12(acc, A, B);
    }
    if (lane == 0) {
        uint4 A = feat[(size_t)node * 2];
        uint4 B = feat[(size_t)node * 2 + 1];
        acc12(acc, A, B);
    }
    #pragma unroll
    for (int off = 1; off <= 2; off <<= 1) {
        #pragma unroll
        for (int j = 0; j < 12; ++j)
            acc[j] += __shfl_xor_sync(0xffffffffu, acc[j], off);
    }
}

// Gather layer 1 + epilogue: u = fp16( relu(dinv*sum + b1) * dinv )
__global__ void k_gather_u(const float* __restrict__ b1v, int n) {
    __shared__ float bs[12];
    if (threadIdx.x < 12) bs[threadIdx.x] = b1v[threadIdx.x];
    __syncthreads();

    int g = blockIdx.x * blockDim.x + threadIdx.x;
    int node = g >> 2;
    int lane = g & 3;
    bool valid = (node < n);
    if (node >= n) node = n - 1;

    float acc[12];
    gather12_c4(g_g1h, node, lane, acc);

    if (valid && lane == 0) {
        float dn = g_dinv[node];
        float u[12];
        #pragma unroll
        for (int j = 0; j < 12; ++j)
            u[j] = fmaxf(dn * acc[j] + bs[j], 0.0f) * dn;
        uint4 A, B;
        A.x = pack2(u[0], u[1]);
        A.y = pack2(u[2], u[3]);
        A.z = pack2(u[4], u[5]);
        A.w = pack2(u[6], u[7]);
        B.x = pack2(u[8], u[9]);
        B.y = pack2(u[10], u[11]);
        B.z = 0; B.w = 0;
        g_uh[(size_t)node * 2]     = A;
        g_uh[(size_t)node * 2 + 1] = B;
    }
}

// Gather layer 2: v = dinv * (sum_in u + u[self])   (12 fp32 per node)
__global__ void k_gather_v(int n) {
    int g = blockIdx.x * blockDim.x + threadIdx.x;
    int node = g >> 2;
    int lane = g & 3;
    bool valid = (node < n);
    if (node >= n) node = n - 1;

    float acc[12];
    gather12_c4(g_uh, node, lane, acc);

    if (valid && lane == 0) {
        float dn = g_dinv[node];
        float4* out4 = (float4*)g_v + (size_t)node * 3;
        out4[0] = make_float4(dn * acc[0], dn * acc[1], dn * acc[2],  dn * acc[3]);
        out4[1] = make_float4(dn * acc[4], dn * acc[5], dn * acc[6],  dn * acc[7]);
        out4[2] = make_float4(dn * acc[8], dn * acc[9], dn * acc[10], dn * acc[11]);
    }
}

// ---------------------------------------------------------------------------
// MLP epilogue: h2 = relu(v@W2+b2); h3 = relu(h2@Wf1+bf1); out = h3@Wf2+bf2
__global__ void k_mlp(const float* __restrict__ W2, const float* __restrict__ b2v,
                      const float* __restrict__ Wf1, const float* __restrict__ bf1,
                      const float* __restrict__ Wf2, const float* __restrict__ bf2,
                      float* __restrict__ out, int n) {
    __shared__ float W2s[12 * 24];
    __shared__ float Wf1s[24 * 32];
    __shared__ float Wf2s[32 * 2];
    __shared__ float b2s[24], bf1s[32], bf2s[2];
    for (int i = threadIdx.x; i < 12 * 24; i += blockDim.x) W2s[i] = W2[i];
    for (int i = threadIdx.x; i < 24 * 32; i += blockDim.x) Wf1s[i] = Wf1[i];
    if (threadIdx.x < 64) Wf2s[threadIdx.x] = Wf2[threadIdx.x];
    if (threadIdx.x < 24) b2s[threadIdx.x] = b2v[threadIdx.x];
    if (threadIdx.x < 32) bf1s[threadIdx.x] = bf1[threadIdx.x];
    if (threadIdx.x < 2)  bf2s[threadIdx.x] = bf2[threadIdx.x];
    __syncthreads();

    int node = blockIdx.x * blockDim.x + threadIdx.x;
    if (node >= n) return;

    const float4* v4 = (const float4*)g_v + (size_t)node * 3;
    float4 v0 = v4[0], v1 = v4[1], v2 = v4[2];
    float v[12] = { v0.x, v0.y, v0.z, v0.w, v1.x, v1.y, v1.z, v1.w, v2.x, v2.y, v2.z, v2.w };

    float h2[24];
    #pragma unroll
    for (int j2 = 0; j2 < 24; ++j2) h2[j2] = b2s[j2];
    #pragma unroll
    for (int j = 0; j < 12; ++j) {
        float hv = v[j];
        const float* wr = W2s + j * 24;
        #pragma unroll
        for (int j2 = 0; j2 < 24; ++j2) h2[j2] += hv * wr[j2];
    }
    #pragma unroll
    for (int j2 = 0; j2 < 24; ++j2) h2[j2] = fmaxf(h2[j2], 0.0f);

    float h3[32];
    #pragma unroll
    for (int o = 0; o < 32; ++o) h3[o] = bf1s[o];
    #pragma unroll
    for (int j = 0; j < 24; ++j) {
        float hv = h2[j];
        const float* wr = Wf1s + j * 32;
        #pragma unroll
        for (int o = 0; o < 32; ++o) h3[o] += hv * wr[o];
    }
    #pragma unroll
    for (int o = 0; o < 32; ++o) h3[o] = fmaxf(h3[o], 0.0f);

    float o0 = bf2s[0], o1 = bf2s[1];
    #pragma unroll
    for (int o = 0; o < 32; ++o) {
        o0 += h3[o] * Wf2s[o * 2 + 0];
        o1 += h3[o] * Wf2s[o * 2 + 1];
    }
    ((float2*)out)[node] = make_float2(o0, o1);
}

// ---------------------------------------------------------------------------
extern "C" void kernel_launch(void* const* d_in, const int* in_sizes, int n_in,
                              void* d_out, int out_size) {
    const float* x   = (const float*)d_in[0];
    const void*  ei  = d_in[1];
    const float* W1  = (const float*)d_in[2];
    const float* b1  = (const float*)d_in[3];
    const float* W2  = (const float*)d_in[4];
    const float* b2  = (const float*)d_in[5];
    const float* Wf1 = (const float*)d_in[6];
    const float* bf1 = (const float*)d_in[7];
    const float* Wf2 = (const float*)d_in[8];
    const float* bf2 = (const float*)d_in[9];
    float* out = (float*)d_out;

    const int n = in_sizes[0] / FIN;       // 200000
    const int e = in_sizes[1] / 2;         // 6400000
    const int equads = (e + 3) / 4;

    const int T = 256;
    k_zero_detect<<<(n + T - 1) / T, T>>>((const int*)ei, n);
    k_deg_convert<<<(equads + T - 1) / T, T>>>(ei, e);
    k_scan1<<<NB1, SCAN_T>>>(n);
    k_scan2<<<1, 128>>>();
    k_scan3<<<(n + T - 1) / T, T>>>(n);
    k_fill<<<(equads + T - 1) / T, T>>>(e);
    k_gemm1<<<((n + 1) / 2 + T - 1) / T, T>>>(x, W1, n);
    k_gather_u<<<(n * 4 + T - 1) / T, T>>>(b1, n);
    k_gather_v<<<(n * 4 + T - 1) / T, T>>>(n);
    k_mlp<<<(n + T - 1) / T, T>>>(W2, b2, Wf1, bf1, Wf2, bf2, out, n);
}

// round 10
// speedup vs baseline: 1.8212x; 1.1143x over previous
#include <cuda_runtime.h>
#include <cuda_fp16.h>

#define NN 200000
#define EE 6400000
#define FIN 128

#define SCAN_T 256
#define SCAN_E 8
#define SCAN_CHUNK (SCAN_T * SCAN_E)                    // 2048
#define NB1 ((NN + SCAN_CHUNK - 1) / SCAN_CHUNK)        // 98

// Scratch (static __device__ — no allocation allowed; zero-initialized at load)
__device__ int   g_deg[NN];              // zeroed at end of each replay by k_mlp
__device__ float g_dinv[NN];
__device__ int   g_start[NN];
__device__ int   g_cursor[NN];
__device__ int   g_src[EE];
__device__ uint4 g_g1h[NN * 2];          // fp16 (x@W1)*dinv, 12 halves + 4 pad (32B/node)
__device__ uint4 g_uh[NN * 2];           // fp16 relu(layer1)*dinv
__device__ float g_v[NN * 12];           // fp32 layer-2 aggregate (pre-MLP)
__device__ int   g_bsum[NB1];

// ---------------------------------------------------------------------------
__device__ __forceinline__ bool is_idx64(const void* ei) {
    const int4* p = (const int4*)ei;
    int4 a = __ldg(p);
    int4 b = __ldg(p + 1);
    return ((a.y | a.w | b.y | b.w) == 0);
}

__device__ __forceinline__ unsigned pack2(float a, float b) {
    __half2 h = __floats2half2_rn(a, b);
    return *reinterpret_cast<unsigned*>(&h);
}
__device__ __forceinline__ void add2(float& a, float& b, unsigned u) {
    __half2 h = *reinterpret_cast<__half2*>(&u);
    float2 f = __half22float2(h);
    a += f.x; b += f.y;
}
__device__ __forceinline__ void acc12(float* acc, uint4 A, uint4 B) {
    add2(acc[0],  acc[1],  A.x);
    add2(acc[2],  acc[3],  A.y);
    add2(acc[4],  acc[5],  A.z);
    add2(acc[6],  acc[7],  A.w);
    add2(acc[8],  acc[9],  B.x);
    add2(acc[10], acc[11], B.y);
}

// ---------------------------------------------------------------------------
// Degree histogram over targets. Reads only the col half of the edge index.
__global__ void k_deg(const void* __restrict__ ei, int ecnt) {
    int t  = blockIdx.x * blockDim.x + threadIdx.x;
    int e0 = t * 4;
    if (e0 >= ecnt) return;
    bool i64 = is_idx64(ei);
    if (e0 + 3 < ecnt) {
        int c0, c1, c2, c3;
        if (i64) {
            const longlong2* pc = (const longlong2*)((const long long*)ei + ecnt + e0);
            longlong2 c01 = __ldcs(pc), c23 = __ldcs(pc + 1);
            c0 = (int)c01.x; c1 = (int)c01.y; c2 = (int)c23.x; c3 = (int)c23.y;
        } else {
            int4 cv = __ldcs((const int4*)((const int*)ei + ecnt + e0));
            c0 = cv.x; c1 = cv.y; c2 = cv.z; c3 = cv.w;
        }
        atomicAdd(&g_deg[c0], 1);
        atomicAdd(&g_deg[c1], 1);
        atomicAdd(&g_deg[c2], 1);
        atomicAdd(&g_deg[c3], 1);
    } else {
        for (int e = e0; e < ecnt; ++e) {
            int cc = i64 ? (int)((const long long*)ei)[(long long)ecnt + e]
                         : ((const int*)ei)[ecnt + e];
            atomicAdd(&g_deg[cc], 1);
        }
    }
}

// ---------------------------------------------------------------------------
// Exclusive scan of g_deg -> g_start
__global__ void k_scan1(int n) {
    __shared__ int ts[SCAN_T];
    int base = blockIdx.x * SCAN_CHUNK + threadIdx.x * SCAN_E;
    int v[SCAN_E];
    int sum = 0;
    #pragma unroll
    for (int j = 0; j < SCAN_E; ++j) {
        int idx = base + j;
        v[j] = (idx < n) ? g_deg[idx] : 0;
        sum += v[j];
    }
    ts[threadIdx.x] = sum;
    __syncthreads();
    for (int off = 1; off < SCAN_T; off <<= 1) {
        int t = (threadIdx.x >= off) ? ts[threadIdx.x - off] : 0;
        __syncthreads();
        ts[threadIdx.x] += t;
        __syncthreads();
    }
    int run = ts[threadIdx.x] - sum;
    if (threadIdx.x == SCAN_T - 1) g_bsum[blockIdx.x] = ts[SCAN_T - 1];
    #pragma unroll
    for (int j = 0; j < SCAN_E; ++j) {
        int idx = base + j;
        if (idx < n) g_start[idx] = run;
        run += v[j];
    }
}

__global__ void k_scan2() {
    __shared__ int ts[128];
    int t = threadIdx.x;
    int v = (t < NB1) ? g_bsum[t] : 0;
    ts[t] = v;
    __syncthreads();
    for (int off = 1; off < 128; off <<= 1) {
        int w = (t >= off) ? ts[t - off] : 0;
        __syncthreads();
        ts[t] += w;
        __syncthreads();
    }
    if (t < NB1) g_bsum[t] = ts[t] - v;
}

__global__ void k_scan3(int n) {
    int i = blockIdx.x * blockDim.x + threadIdx.x;
    if (i >= n) return;
    int s = g_start[i] + g_bsum[i / SCAN_CHUNK];
    g_start[i]  = s;
    g_cursor[i] = s;
    g_dinv[i]   = rsqrtf((float)(g_deg[i] + 1));
}

// ---------------------------------------------------------------------------
// CSR fill directly from the original edge index. 4 edges/thread.
__global__ void k_fill(const void* __restrict__ ei, int ecnt) {
    int t  = blockIdx.x * blockDim.x + threadIdx.x;
    int e0 = t * 4;
    if (e0 >= ecnt) return;
    bool i64 = is_idx64(ei);
    if (e0 + 3 < ecnt) {
        int r0, r1, r2, r3, c0, c1, c2, c3;
        if (i64) {
            const longlong2* pr = (const longlong2*)((const long long*)ei + e0);
            const longlong2* pc = (const longlong2*)((const long long*)ei + ecnt + e0);
            longlong2 r01 = __ldcs(pr), r23 = __ldcs(pr + 1);
            longlong2 c01 = __ldcs(pc), c23 = __ldcs(pc + 1);
            r0 = (int)r01.x; r1 = (int)r01.y; r2 = (int)r23.x; r3 = (int)r23.y;
            c0 = (int)c01.x; c1 = (int)c01.y; c2 = (int)c23.x; c3 = (int)c23.y;
        } else {
            int4 rv = __ldcs((const int4*)((const int*)ei + e0));
            int4 cv = __ldcs((const int4*)((const int*)ei + ecnt + e0));
            r0 = rv.x; r1 = rv.y; r2 = rv.z; r3 = rv.w;
            c0 = cv.x; c1 = cv.y; c2 = cv.z; c3 = cv.w;
        }
        int s0 = atomicAdd(&g_cursor[c0], 1);
        int s1 = atomicAdd(&g_cursor[c1], 1);
        int s2 = atomicAdd(&g_cursor[c2], 1);
        int s3 = atomicAdd(&g_cursor[c3], 1);
        g_src[s0] = r0;
        g_src[s1] = r1;
        g_src[s2] = r2;
        g_src[s3] = r3;
    } else {
        for (int e = e0; e < ecnt; ++e) {
            int rr, cc;
            if (i64) {
                const long long* p = (const long long*)ei;
                rr = (int)p[e]; cc = (int)p[(long long)ecnt + e];
            } else {
                const int* p = (const int*)ei;
                rr = p[e]; cc = p[ecnt + e];
            }
            int s = atomicAdd(&g_cursor[cc], 1);
            g_src[s] = rr;
        }
    }
}

// ---------------------------------------------------------------------------
// GEMM1: g1h[n] = fp16( dinv[n] * (x[n] @ W1) )
__device__ __forceinline__ float comp4(const float4& v, int kk) {
    return kk == 0 ? v.x : kk == 1 ? v.y : kk == 2 ? v.z : v.w;
}

__global__ void k_gemm1(const float* __restrict__ x, const float* __restrict__ W1, int n) {
    __shared__ float Ws[FIN * 12];
    for (int i = threadIdx.x; i < FIN * 12; i += blockDim.x) Ws[i] = W1[i];
    __syncthreads();

    int g  = blockIdx.x * blockDim.x + threadIdx.x;
    int n0 = g * 2;
    if (n0 >= n) return;
    bool two = (n0 + 1 < n);

    float a0[12], a1v[12];
    #pragma unroll
    for (int j = 0; j < 12; ++j) { a0[j] = 0.0f; a1v[j] = 0.0f; }

    const float4* xr0 = (const float4*)x + (size_t)n0 * (FIN / 4);
    const float4* xr1 = xr0 + (FIN / 4);

    #pragma unroll 4
    for (int k4 = 0; k4 < FIN / 4; ++k4) {
        float4 a = __ldcs(xr0 + k4);
        float4 b = two ? __ldcs(xr1 + k4) : make_float4(0.f, 0.f, 0.f, 0.f);
        #pragma unroll
        for (int kk = 0; kk < 4; ++kk) {
            const float4* wp = (const float4*)(Ws + (k4 * 4 + kk) * 12);
            float4 w0 = wp[0], w1 = wp[1], w2 = wp[2];
            float xa = comp4(a, kk);
            float xb = comp4(b, kk);
            a0[0]  += xa * w0.x; a0[1]  += xa * w0.y; a0[2]  += xa * w0.z; a0[3]  += xa * w0.w;
            a0[4]  += xa * w1.x; a0[5]  += xa * w1.y; a0[6]  += xa * w1.z; a0[7]  += xa * w1.w;
            a0[8]  += xa * w2.x; a0[9]  += xa * w2.y; a0[10] += xa * w2.z; a0[11] += xa * w2.w;
            a1v[0]  += xb * w0.x; a1v[1]  += xb * w0.y; a1v[2]  += xb * w0.z; a1v[3]  += xb * w0.w;
            a1v[4]  += xb * w1.x; a1v[5]  += xb * w1.y; a1v[6]  += xb * w1.z; a1v[7]  += xb * w1.w;
            a1v[8]  += xb * w2.x; a1v[9]  += xb * w2.y; a1v[10] += xb * w2.z; a1v[11] += xb * w2.w;
        }
    }

    {
        float dn = g_dinv[n0];
        uint4 A, B;
        A.x = pack2(a0[0] * dn, a0[1] * dn);
        A.y = pack2(a0[2] * dn, a0[3] * dn);
        A.z = pack2(a0[4] * dn, a0[5] * dn);
        A.w = pack2(a0[6] * dn, a0[7] * dn);
        B.x = pack2(a0[8] * dn, a0[9] * dn);
        B.y = pack2(a0[10] * dn, a0[11] * dn);
        B.z = 0; B.w = 0;
        g_g1h[(size_t)n0 * 2]     = A;
        g_g1h[(size_t)n0 * 2 + 1] = B;
    }
    if (two) {
        float dn = g_dinv[n0 + 1];
        uint4 A, B;
        A.x = pack2(a1v[0] * dn, a1v[1] * dn);
        A.y = pack2(a1v[2] * dn, a1v[3] * dn);
        A.z = pack2(a1v[4] * dn, a1v[5] * dn);
        A.w = pack2(a1v[6] * dn, a1v[7] * dn);
        B.x = pack2(a1v[8] * dn, a1v[9] * dn);
        B.y = pack2(a1v[10] * dn, a1v[11] * dn);
        B.z = 0; B.w = 0;
        g_g1h[(size_t)(n0 + 1) * 2]     = A;
        g_g1h[(size_t)(n0 + 1) * 2 + 1] = B;
    }
}

// ---------------------------------------------------------------------------
// 4-lane cooperative gather, 2 edges/lane in flight. All lanes converged.
__device__ __forceinline__ void gather12_c4(const uint4* __restrict__ feat,
                                            int node, int lane, float* acc) {
    int s = g_start[node];
    int end = s + g_deg[node];

    #pragma unroll
    for (int j = 0; j < 12; ++j) acc[j] = 0.0f;

    int i = s + lane;
    for (; i + 4 < end; i += 8) {
        int r0 = __ldg(&g_src[i]);
        int r1 = __ldg(&g_src[i + 4]);
        uint4 A0 = __ldg(feat + (size_t)r0 * 2), B0 = __ldg(feat + (size_t)r0 * 2 + 1);
        uint4 A1 = __ldg(feat + (size_t)r1 * 2), B1 = __ldg(feat + (size_t)r1 * 2 + 1);
        acc12(acc, A0, B0);
        acc12(acc, A1, B1);
    }
    if (i < end) {
        int r0 = __ldg(&g_src[i]);
        uint4 A0 = __ldg(feat + (size_t)r0 * 2), B0 = __ldg(feat + (size_t)r0 * 2 + 1);
        acc12(acc, A0, B0);
    }
    if (lane == 0) {
        uint4 A = feat[(size_t)node * 2];
        uint4 B = feat[(size_t)node * 2 + 1];
        acc12(acc, A, B);
    }
    #pragma unroll
    for (int off = 1; off <= 2; off <<= 1) {
        #pragma unroll
        for (int j = 0; j < 12; ++j)
            acc[j] += __shfl_xor_sync(0xffffffffu, acc[j], off);
    }
}

// Gather layer 1 + epilogue: u = fp16( relu(dinv*sum + b1) * dinv )
__global__ void k_gather_u(const float* __restrict__ b1v, int n) {
    __shared__ float bs[12];
    if (threadIdx.x < 12) bs[threadIdx.x] = b1v[threadIdx.x];
    __syncthreads();

    int g = blockIdx.x * blockDim.x + threadIdx.x;
    int node = g >> 2;
    int lane = g & 3;
    bool valid = (node < n);
    if (node >= n) node = n - 1;

    float acc[12];
    gather12_c4(g_g1h, node, lane, acc);

    if (valid && lane == 0) {
        float dn = g_dinv[node];
        float u[12];
        #pragma unroll
        for (int j = 0; j < 12; ++j)
            u[j] = fmaxf(dn * acc[j] + bs[j], 0.0f) * dn;
        uint4 A, B;
        A.x = pack2(u[0], u[1]);
        A.y = pack2(u[2], u[3]);
        A.z = pack2(u[4], u[5]);
        A.w = pack2(u[6], u[7]);
        B.x = pack2(u[8], u[9]);
        B.y = pack2(u[10], u[11]);
        B.z = 0; B.w = 0;
        g_uh[(size_t)node * 2]     = A;
        g_uh[(size_t)node * 2 + 1] = B;
    }
}

// Gather layer 2: v = dinv * (sum_in u + u[self])
__global__ void k_gather_v(int n) {
    int g = blockIdx.x * blockDim.x + threadIdx.x;
    int node = g >> 2;
    int lane = g & 3;
    bool valid = (node < n);
    if (node >= n) node = n - 1;

    float acc[12];
    gather12_c4(g_uh, node, lane, acc);

    if (valid && lane == 0) {
        float dn = g_dinv[node];
        float4* out4 = (float4*)g_v + (size_t)node * 3;
        out4[0] = make_float4(dn * acc[0], dn * acc[1], dn * acc[2],  dn * acc[3]);
        out4[1] = make_float4(dn * acc[4], dn * acc[5], dn * acc[6],  dn * acc[7]);
        out4[2] = make_float4(dn * acc[8], dn * acc[9], dn * acc[10], dn * acc[11]);
    }
}

// ---------------------------------------------------------------------------
// MLP epilogue + re-zero g_deg for the next graph replay.
__global__ void k_mlp(const float* __restrict__ W2, const float* __restrict__ b2v,
                      const float* __restrict__ Wf1, const float* __restrict__ bf1,
                      const float* __restrict__ Wf2, const float* __restrict__ bf2,
                      float* __restrict__ out, int n) {
    __shared__ float W2s[12 * 24];
    __shared__ float Wf1s[24 * 32];
    __shared__ float Wf2s[32 * 2];
    __shared__ float b2s[24], bf1s[32], bf2s[2];
    for (int i = threadIdx.x; i < 12 * 24; i += blockDim.x) W2s[i] = W2[i];
    for (int i = threadIdx.x; i < 24 * 32; i += blockDim.x) Wf1s[i] = Wf1[i];
    if (threadIdx.x < 64) Wf2s[threadIdx.x] = Wf2[threadIdx.x];
    if (threadIdx.x < 24) b2s[threadIdx.x] = b2v[threadIdx.x];
    if (threadIdx.x < 32) bf1s[threadIdx.x] = bf1[threadIdx.x];
    if (threadIdx.x < 2)  bf2s[threadIdx.x] = bf2[threadIdx.x];
    __syncthreads();

    int node = blockIdx.x * blockDim.x + threadIdx.x;
    if (node >= n) return;

    g_deg[node] = 0;   // reset for next replay (deterministic: every replay re-accumulates)

    const float4* v4 = (const float4*)g_v + (size_t)node * 3;
    float4 v0 = v4[0], v1 = v4[1], v2 = v4[2];
    float v[12] = { v0.x, v0.y, v0.z, v0.w, v1.x, v1.y, v1.z, v1.w, v2.x, v2.y, v2.z, v2.w };

    float h2[24];
    #pragma unroll
    for (int j2 = 0; j2 < 24; ++j2) h2[j2] = b2s[j2];
    #pragma unroll
    for (int j = 0; j < 12; ++j) {
        float hv = v[j];
        const float* wr = W2s + j * 24;
        #pragma unroll
        for (int j2 = 0; j2 < 24; ++j2) h2[j2] += hv * wr[j2];
    }
    #pragma unroll
    for (int j2 = 0; j2 < 24; ++j2) h2[j2] = fmaxf(h2[j2], 0.0f);

    float h3[32];
    #pragma unroll
    for (int o = 0; o < 32; ++o) h3[o] = bf1s[o];
    #pragma unroll
    for (int j = 0; j < 24; ++j) {
        float hv = h2[j];
        const float* wr = Wf1s + j * 32;
        #pragma unroll
        for (int o = 0; o < 32; ++o) h3[o] += hv * wr[o];
    }
    #pragma unroll
    for (int o = 0; o < 32; ++o) h3[o] = fmaxf(h3[o], 0.0f);

    float o0 = bf2s[0], o1 = bf2s[1];
    #pragma unroll
    for (int o = 0; o < 32; ++o) {
        o0 += h3[o] * Wf2s[o * 2 + 0];
        o1 += h3[o] * Wf2s[o * 2 + 1];
    }
    ((float2*)out)[node] = make_float2(o0, o1);
}

// ---------------------------------------------------------------------------
extern "C" void kernel_launch(void* const* d_in, const int* in_sizes, int n_in,
                              void* d_out, int out_size) {
    const float* x   = (const float*)d_in[0];
    const void*  ei  = d_in[1];
    const float* W1  = (const float*)d_in[2];
    const float* b1  = (const float*)d_in[3];
    const float* W2  = (const float*)d_in[4];
    const float* b2  = (const float*)d_in[5];
    const float* Wf1 = (const float*)d_in[6];
    const float* bf1 = (const float*)d_in[7];
    const float* Wf2 = (const float*)d_in[8];
    const float* bf2 = (const float*)d_in[9];
    float* out = (float*)d_out;

    const int n = in_sizes[0] / FIN;       // 200000
    const int e = in_sizes[1] / 2;         // 6400000
    const int equads = (e + 3) / 4;

    const int T = 256;
    k_deg<<<(equads + T - 1) / T, T>>>(ei, e);
    k_scan1<<<NB1, SCAN_T>>>(n);
    k_scan2<<<1, 128>>>();
    k_scan3<<<(n + T - 1) / T, T>>>(n);
    k_fill<<<(equads + T - 1) / T, T>>>(ei, e);
    k_gemm1<<<((n + 1) / 2 + T - 1) / T, T>>>(x, W1, n);
    k_gather_u<<<(n * 4 + T - 1) / T, T>>>(b1, n);
    k_gather_v<<<(n * 4 + T - 1) / T, T>>>(n);
    k_mlp<<<(n + T - 1) / T, T>>>(W2, b2, Wf1, bf1, Wf2, bf2, out, n);
}

// round 11
// speedup vs baseline: 1.9118x; 1.0497x over previous
#include <cuda_runtime.h>
#include <cuda_fp16.h>

#define NN 200000
#define EE 6400000
#define FIN 128

#define SCAN_T 256
#define SCAN_E 8
#define SCAN_CHUNK (SCAN_T * SCAN_E)                    // 2048
#define NB1 ((NN + SCAN_CHUNK - 1) / SCAN_CHUNK)        // 98

// Scratch (static __device__ — no allocation allowed; zero-initialized at load)
__device__ int   g_deg[NN];              // zeroed at end of each replay by k_mlp
__device__ float g_dinv[NN];
__device__ int   g_start[NN];
__device__ int   g_cursor[NN];
__device__ int   g_src[EE];
__device__ uint4 g_g1h[NN * 2];          // fp16 (x@W1)*dinv, 12 halves + 4 pad (32B/node)
__device__ uint4 g_uh[NN * 2];           // fp16 relu(layer1)*dinv
__device__ float g_v[NN * 12];           // fp32 layer-2 aggregate (pre-MLP)
__device__ int   g_bsum[NB1];

// ---------------------------------------------------------------------------
__device__ __forceinline__ bool is_idx64(const void* ei) {
    const int4* p = (const int4*)ei;
    int4 a = __ldg(p);
    int4 b = __ldg(p + 1);
    return ((a.y | a.w | b.y | b.w) == 0);
}

__device__ __forceinline__ unsigned pack2(float a, float b) {
    __half2 h = __floats2half2_rn(a, b);
    return *reinterpret_cast<unsigned*>(&h);
}
__device__ __forceinline__ void add2(float& a, float& b, unsigned u) {
    __half2 h = *reinterpret_cast<__half2*>(&u);
    float2 f = __half22float2(h);
    a += f.x; b += f.y;
}
__device__ __forceinline__ void acc12(float* acc, uint4 A, uint4 B) {
    add2(acc[0],  acc[1],  A.x);
    add2(acc[2],  acc[3],  A.y);
    add2(acc[4],  acc[5],  A.z);
    add2(acc[6],  acc[7],  A.w);
    add2(acc[8],  acc[9],  B.x);
    add2(acc[10], acc[11], B.y);
}

// ---------------------------------------------------------------------------
// Degree histogram over targets (col half only).
__global__ void k_deg(const void* __restrict__ ei, int ecnt) {
    int t  = blockIdx.x * blockDim.x + threadIdx.x;
    int e0 = t * 4;
    if (e0 >= ecnt) return;
    bool i64 = is_idx64(ei);
    if (e0 + 3 < ecnt) {
        int c0, c1, c2, c3;
        if (i64) {
            const longlong2* pc = (const longlong2*)((const long long*)ei + ecnt + e0);
            longlong2 c01 = __ldcs(pc), c23 = __ldcs(pc + 1);
            c0 = (int)c01.x; c1 = (int)c01.y; c2 = (int)c23.x; c3 = (int)c23.y;
        } else {
            int4 cv = __ldcs((const int4*)((const int*)ei + ecnt + e0));
            c0 = cv.x; c1 = cv.y; c2 = cv.z; c3 = cv.w;
        }
        atomicAdd(&g_deg[c0], 1);
        atomicAdd(&g_deg[c1], 1);
        atomicAdd(&g_deg[c2], 1);
        atomicAdd(&g_deg[c3], 1);
    } else {
        for (int e = e0; e < ecnt; ++e) {
            int cc = i64 ? (int)((const long long*)ei)[(long long)ecnt + e]
                         : ((const int*)ei)[ecnt + e];
            atomicAdd(&g_deg[cc], 1);
        }
    }
}

// ---------------------------------------------------------------------------
// Scan pass 1: per-chunk exclusive scan + chunk sums.
__global__ void k_scan1(int n) {
    __shared__ int ts[SCAN_T];
    int base = blockIdx.x * SCAN_CHUNK + threadIdx.x * SCAN_E;
    int v[SCAN_E];
    int sum = 0;
    #pragma unroll
    for (int j = 0; j < SCAN_E; ++j) {
        int idx = base + j;
        v[j] = (idx < n) ? g_deg[idx] : 0;
        sum += v[j];
    }
    ts[threadIdx.x] = sum;
    __syncthreads();
    for (int off = 1; off < SCAN_T; off <<= 1) {
        int t = (threadIdx.x >= off) ? ts[threadIdx.x - off] : 0;
        __syncthreads();
        ts[threadIdx.x] += t;
        __syncthreads();
    }
    int run = ts[threadIdx.x] - sum;
    if (threadIdx.x == SCAN_T - 1) g_bsum[blockIdx.x] = ts[SCAN_T - 1];
    #pragma unroll
    for (int j = 0; j < SCAN_E; ++j) {
        int idx = base + j;
        if (idx < n) g_start[idx] = run;
        run += v[j];
    }
}

// Scan pass 2+3 merged: every block redundantly scans the 98 chunk sums in
// shared, then finalizes start/cursor/dinv for its 256 nodes.
__global__ void k_scan23(int n) {
    __shared__ int ts[SCAN_T];   // inclusive scan of chunk sums
    int t = threadIdx.x;
    int v = (t < NB1) ? g_bsum[t] : 0;
    ts[t] = v;
    __syncthreads();
    for (int off = 1; off < SCAN_T; off <<= 1) {
        int w = (t >= off) ? ts[t - off] : 0;
        __syncthreads();
        ts[t] += w;
        __syncthreads();
    }

    int i = blockIdx.x * blockDim.x + threadIdx.x;
    if (i >= n) return;
    int chunk = i / SCAN_CHUNK;
    int base = (chunk == 0) ? 0 : ts[chunk - 1];
    int s = g_start[i] + base;
    g_start[i]  = s;
    g_cursor[i] = s;
    g_dinv[i]   = rsqrtf((float)(g_deg[i] + 1));
}

// ---------------------------------------------------------------------------
// Fused: GEMM1 (blocks [0, nb_gemm)) + CSR fill (blocks [nb_gemm, ...)).
// Both depend only on the scan; they overlap via SM partitioning.
__device__ __forceinline__ float comp4(const float4& v, int kk) {
    return kk == 0 ? v.x : kk == 1 ? v.y : kk == 2 ? v.z : v.w;
}

__global__ void k_fill_gemm(const void* __restrict__ ei, int ecnt,
                            const float* __restrict__ x, const float* __restrict__ W1,
                            int n, int nb_gemm) {
    __shared__ float Ws[FIN * 12];

    if (blockIdx.x < nb_gemm) {
        // ---------------- GEMM1: g1h[n] = fp16( dinv[n] * (x[n] @ W1) ) ----
        for (int i = threadIdx.x; i < FIN * 12; i += blockDim.x) Ws[i] = W1[i];
        __syncthreads();

        int g  = blockIdx.x * blockDim.x + threadIdx.x;
        int n0 = g * 2;
        if (n0 >= n) return;
        bool two = (n0 + 1 < n);

        float a0[12], a1v[12];
        #pragma unroll
        for (int j = 0; j < 12; ++j) { a0[j] = 0.0f; a1v[j] = 0.0f; }

        const float4* xr0 = (const float4*)x + (size_t)n0 * (FIN / 4);
        const float4* xr1 = xr0 + (FIN / 4);

        #pragma unroll 4
        for (int k4 = 0; k4 < FIN / 4; ++k4) {
            float4 a = __ldcs(xr0 + k4);
            float4 b = two ? __ldcs(xr1 + k4) : make_float4(0.f, 0.f, 0.f, 0.f);
            #pragma unroll
            for (int kk = 0; kk < 4; ++kk) {
                const float4* wp = (const float4*)(Ws + (k4 * 4 + kk) * 12);
                float4 w0 = wp[0], w1 = wp[1], w2 = wp[2];
                float xa = comp4(a, kk);
                float xb = comp4(b, kk);
                a0[0]  += xa * w0.x; a0[1]  += xa * w0.y; a0[2]  += xa * w0.z; a0[3]  += xa * w0.w;
                a0[4]  += xa * w1.x; a0[5]  += xa * w1.y; a0[6]  += xa * w1.z; a0[7]  += xa * w1.w;
                a0[8]  += xa * w2.x; a0[9]  += xa * w2.y; a0[10] += xa * w2.z; a0[11] += xa * w2.w;
                a1v[0]  += xb * w0.x; a1v[1]  += xb * w0.y; a1v[2]  += xb * w0.z; a1v[3]  += xb * w0.w;
                a1v[4]  += xb * w1.x; a1v[5]  += xb * w1.y; a1v[6]  += xb * w1.z; a1v[7]  += xb * w1.w;
                a1v[8]  += xb * w2.x; a1v[9]  += xb * w2.y; a1v[10] += xb * w2.z; a1v[11] += xb * w2.w;
            }
        }

        {
            float dn = g_dinv[n0];
            uint4 A, B;
            A.x = pack2(a0[0] * dn, a0[1] * dn);
            A.y = pack2(a0[2] * dn, a0[3] * dn);
            A.z = pack2(a0[4] * dn, a0[5] * dn);
            A.w = pack2(a0[6] * dn, a0[7] * dn);
            B.x = pack2(a0[8] * dn, a0[9] * dn);
            B.y = pack2(a0[10] * dn, a0[11] * dn);
            B.z = 0; B.w = 0;
            g_g1h[(size_t)n0 * 2]     = A;
            g_g1h[(size_t)n0 * 2 + 1] = B;
        }
        if (two) {
            float dn = g_dinv[n0 + 1];
            uint4 A, B;
            A.x = pack2(a1v[0] * dn, a1v[1] * dn);
            A.y = pack2(a1v[2] * dn, a1v[3] * dn);
            A.z = pack2(a1v[4] * dn, a1v[5] * dn);
            A.w = pack2(a1v[6] * dn, a1v[7] * dn);
            B.x = pack2(a1v[8] * dn, a1v[9] * dn);
            B.y = pack2(a1v[10] * dn, a1v[11] * dn);
            B.z = 0; B.w = 0;
            g_g1h[(size_t)(n0 + 1) * 2]     = A;
            g_g1h[(size_t)(n0 + 1) * 2 + 1] = B;
        }
    } else {
        // ---------------- CSR fill: slot = cursor[col]++ ; src[slot] = row --
        int t  = (blockIdx.x - nb_gemm) * blockDim.x + threadIdx.x;
        int e0 = t * 4;
        if (e0 >= ecnt) return;
        bool i64 = is_idx64(ei);
        if (e0 + 3 < ecnt) {
            int r0, r1, r2, r3, c0, c1, c2, c3;
            if (i64) {
                const longlong2* pr = (const longlong2*)((const long long*)ei + e0);
                const longlong2* pc = (const longlong2*)((const long long*)ei + ecnt + e0);
                longlong2 r01 = __ldcs(pr), r23 = __ldcs(pr + 1);
                longlong2 c01 = __ldcs(pc), c23 = __ldcs(pc + 1);
                r0 = (int)r01.x; r1 = (int)r01.y; r2 = (int)r23.x; r3 = (int)r23.y;
                c0 = (int)c01.x; c1 = (int)c01.y; c2 = (int)c23.x; c3 = (int)c23.y;
            } else {
                int4 rv = __ldcs((const int4*)((const int*)ei + e0));
                int4 cv = __ldcs((const int4*)((const int*)ei + ecnt + e0));
                r0 = rv.x; r1 = rv.y; r2 = rv.z; r3 = rv.w;
                c0 = cv.x; c1 = cv.y; c2 = cv.z; c3 = cv.w;
            }
            int s0 = atomicAdd(&g_cursor[c0], 1);
            int s1 = atomicAdd(&g_cursor[c1], 1);
            int s2 = atomicAdd(&g_cursor[c2], 1);
            int s3 = atomicAdd(&g_cursor[c3], 1);
            g_src[s0] = r0;
            g_src[s1] = r1;
            g_src[s2] = r2;
            g_src[s3] = r3;
        } else {
            for (int e = e0; e < ecnt; ++e) {
                int rr, cc;
                if (i64) {
                    const long long* p = (const long long*)ei;
                    rr = (int)p[e]; cc = (int)p[(long long)ecnt + e];
                } else {
                    const int* p = (const int*)ei;
                    rr = p[e]; cc = p[ecnt + e];
                }
                int s = atomicAdd(&g_cursor[cc], 1);
                g_src[s] = rr;
            }
        }
    }
}

// ---------------------------------------------------------------------------
// 4-lane cooperative gather, 2 edges/lane in flight. All lanes converged.
__device__ __forceinline__ void gather12_c4(const uint4* __restrict__ feat,
                                            int node, int lane, float* acc) {
    int s = g_start[node];
    int end = s + g_deg[node];

    #pragma unroll
    for (int j = 0; j < 12; ++j) acc[j] = 0.0f;

    int i = s + lane;
    for (; i + 4 < end; i += 8) {
        int r0 = __ldg(&g_src[i]);
        int r1 = __ldg(&g_src[i + 4]);
        uint4 A0 = __ldg(feat + (size_t)r0 * 2), B0 = __ldg(feat + (size_t)r0 * 2 + 1);
        uint4 A1 = __ldg(feat + (size_t)r1 * 2), B1 = __ldg(feat + (size_t)r1 * 2 + 1);
        acc12(acc, A0, B0);
        acc12(acc, A1, B1);
    }
    if (i < end) {
        int r0 = __ldg(&g_src[i]);
        uint4 A0 = __ldg(feat + (size_t)r0 * 2), B0 = __ldg(feat + (size_t)r0 * 2 + 1);
        acc12(acc, A0, B0);
    }
    if (lane == 0) {
        uint4 A = feat[(size_t)node * 2];
        uint4 B = feat[(size_t)node * 2 + 1];
        acc12(acc, A, B);
    }
    #pragma unroll
    for (int off = 1; off <= 2; off <<= 1) {
        #pragma unroll
        for (int j = 0; j < 12; ++j)
            acc[j] += __shfl_xor_sync(0xffffffffu, acc[j], off);
    }
}

// Gather layer 1 + epilogue: u = fp16( relu(dinv*sum + b1) * dinv )
__global__ void k_gather_u(const float* __restrict__ b1v, int n) {
    __shared__ float bs[12];
    if (threadIdx.x < 12) bs[threadIdx.x] = b1v[threadIdx.x];
    __syncthreads();

    int g = blockIdx.x * blockDim.x + threadIdx.x;
    int node = g >> 2;
    int lane = g & 3;
    bool valid = (node < n);
    if (node >= n) node = n - 1;

    float acc[12];
    gather12_c4(g_g1h, node, lane, acc);

    if (valid && lane == 0) {
        float dn = g_dinv[node];
        float u[12];
        #pragma unroll
        for (int j = 0; j < 12; ++j)
            u[j] = fmaxf(dn * acc[j] + bs[j], 0.0f) * dn;
        uint4 A, B;
        A.x = pack2(u[0], u[1]);
        A.y = pack2(u[2], u[3]);
        A.z = pack2(u[4], u[5]);
        A.w = pack2(u[6], u[7]);
        B.x = pack2(u[8], u[9]);
        B.y = pack2(u[10], u[11]);
        B.z = 0; B.w = 0;
        g_uh[(size_t)node * 2]     = A;
        g_uh[(size_t)node * 2 + 1] = B;
    }
}

// Gather layer 2: v = dinv * (sum_in u + u[self])
__global__ void k_gather_v(int n) {
    int g = blockIdx.x * blockDim.x + threadIdx.x;
    int node = g >> 2;
    int lane = g & 3;
    bool valid = (node < n);
    if (node >= n) node = n - 1;

    float acc[12];
    gather12_c4(g_uh, node, lane, acc);

    if (valid && lane == 0) {
        float dn = g_dinv[node];
        float4* out4 = (float4*)g_v + (size_t)node * 3;
        out4[0] = make_float4(dn * acc[0], dn * acc[1], dn * acc[2],  dn * acc[3]);
        out4[1] = make_float4(dn * acc[4], dn * acc[5], dn * acc[6],  dn * acc[7]);
        out4[2] = make_float4(dn * acc[8], dn * acc[9], dn * acc[10], dn * acc[11]);
    }
}

// ---------------------------------------------------------------------------
// MLP epilogue + re-zero g_deg for the next graph replay.
__global__ void k_mlp(const float* __restrict__ W2, const float* __restrict__ b2v,
                      const float* __restrict__ Wf1, const float* __restrict__ bf1,
                      const float* __restrict__ Wf2, const float* __restrict__ bf2,
                      float* __restrict__ out, int n) {
    __shared__ float W2s[12 * 24];
    __shared__ float Wf1s[24 * 32];
    __shared__ float Wf2s[32 * 2];
    __shared__ float b2s[24], bf1s[32], bf2s[2];
    for (int i = threadIdx.x; i < 12 * 24; i += blockDim.x) W2s[i] = W2[i];
    for (int i = threadIdx.x; i < 24 * 32; i += blockDim.x) Wf1s[i] = Wf1[i];
    if (threadIdx.x < 64) Wf2s[threadIdx.x] = Wf2[threadIdx.x];
    if (threadIdx.x < 24) b2s[threadIdx.x] = b2v[threadIdx.x];
    if (threadIdx.x < 32) bf1s[threadIdx.x] = bf1[threadIdx.x];
    if (threadIdx.x < 2)  bf2s[threadIdx.x] = bf2[threadIdx.x];
    __syncthreads();

    int node = blockIdx.x * blockDim.x + threadIdx.x;
    if (node >= n) return;

    g_deg[node] = 0;   // reset for next replay

    const float4* v4 = (const float4*)g_v + (size_t)node * 3;
    float4 v0 = v4[0], v1 = v4[1], v2 = v4[2];
    float v[12] = { v0.x, v0.y, v0.z, v0.w, v1.x, v1.y, v1.z, v1.w, v2.x, v2.y, v2.z, v2.w };

    float h2[24];
    #pragma unroll
    for (int j2 = 0; j2 < 24; ++j2) h2[j2] = b2s[j2];
    #pragma unroll
    for (int j = 0; j < 12; ++j) {
        float hv = v[j];
        const float* wr = W2s + j * 24;
        #pragma unroll
        for (int j2 = 0; j2 < 24; ++j2) h2[j2] += hv * wr[j2];
    }
    #pragma unroll
    for (int j2 = 0; j2 < 24; ++j2) h2[j2] = fmaxf(h2[j2], 0.0f);

    float h3[32];
    #pragma unroll
    for (int o = 0; o < 32; ++o) h3[o] = bf1s[o];
    #pragma unroll
    for (int j = 0; j < 24; ++j) {
        float hv = h2[j];
        const float* wr = Wf1s + j * 32;
        #pragma unroll
        for (int o = 0; o < 32; ++o) h3[o] += hv * wr[o];
    }
    #pragma unroll
    for (int o = 0; o < 32; ++o) h3[o] = fmaxf(h3[o], 0.0f);

    float o0 = bf2s[0], o1 = bf2s[1];
    #pragma unroll
    for (int o = 0; o < 32; ++o) {
        o0 += h3[o] * Wf2s[o * 2 + 0];
        o1 += h3[o] * Wf2s[o * 2 + 1];
    }
    ((float2*)out)[node] = make_float2(o0, o1);
}

// ---------------------------------------------------------------------------
extern "C" void kernel_launch(void* const* d_in, const int* in_sizes, int n_in,
                              void* d_out, int out_size) {
    const float* x   = (const float*)d_in[0];
    const void*  ei  = d_in[1];
    const float* W1  = (const float*)d_in[2];
    const float* b1  = (const float*)d_in[3];
    const float* W2  = (const float*)d_in[4];
    const float* b2  = (const float*)d_in[5];
    const float* Wf1 = (const float*)d_in[6];
    const float* bf1 = (const float*)d_in[7];
    const float* Wf2 = (const float*)d_in[8];
    const float* bf2 = (const float*)d_in[9];
    float* out = (float*)d_out;

    const int n = in_sizes[0] / FIN;       // 200000
    const int e = in_sizes[1] / 2;         // 6400000
    const int equads = (e + 3) / 4;

    const int T = 256;
    const int nb_gemm = ((n + 1) / 2 + T - 1) / T;      // 391
    const int nb_fill = (equads + T - 1) / T;           // 6250

    k_deg<<<(equads + T - 1) / T, T>>>(ei, e);
    k_scan1<<<NB1, SCAN_T>>>(n);
    k_scan23<<<(n + T - 1) / T, T>>>(n);
    k_fill_gemm<<<nb_gemm + nb_fill, T>>>(ei, e, x, W1, n, nb_gemm);
    k_gather_u<<<(n * 4 + T - 1) / T, T>>>(b1, n);
    k_gather_v<<<(n * 4 + T - 1) / T, T>>>(n);
    k_mlp<<<(n + T - 1) / T, T>>>(W2, b2, Wf1, bf1, Wf2, bf2, out, n);
}